// round 14
// baseline (speedup 1.0000x reference)
#include <cuda_runtime.h>
#include <cuda.h>
#include <cuda_bf16.h>
#include <cuda_fp16.h>
#include <cstdint>
#include <math.h>

#define Bz   4
#define Tz   1024
#define Cz   1024
#define Hz   16
#define BTz  (Bz*Tz)

typedef __half  f16;
typedef __half2 f162;
typedef unsigned long long u64;

// ---------------- scratch (device globals; no allocation allowed) ----------------
__device__ float g_r [BTz*Cz], g_k [BTz*Cz], g_v [BTz*Cz], g_wd[BTz*Cz];
__device__ float g_a [BTz*Cz], g_g [BTz*Cz], g_aa[BTz*Cz], g_bb[BTz*Cz], g_o [BTz*Cz];

__device__ __align__(256) f16 g_x6[6*BTz*Cz];     // mixed streams, fp16
__device__ __align__(256) f16 g_yg[BTz*Cz];       // (gn(o)+bonus)*g fp16
// LoRA hidden pool [BTz, 256]: cols 0-63 decay, 64-127 a, 128-255 g (fp16)
__device__ __align__(256) f16 g_hid[BTz*256];

// weight pool: all matrices stored TRANSPOSED [N, K] row-major, fp16 hi/lo
#define O_Wr 0
#define O_Wk (Cz*Cz)
#define O_Wv (2*Cz*Cz)
#define O_Wo (3*Cz*Cz)
#define O_L1 (4*Cz*Cz)                  // [256, 1024]: w1t 0-63, a1t 64-127, g1t 128-255
#define O_W2T (O_L1 + 256*Cz)           // [1024, 64]
#define O_A2T (O_W2T + Cz*64)           // [1024, 64]
#define O_G2T (O_A2T + Cz*64)           // [1024, 128]
#define WPOOL (O_G2T + Cz*128)
__device__ __align__(256) f16 g_wh[WPOOL], g_wl[WPOOL];

// ---------------- helpers ----------------
__device__ __forceinline__ uint32_t su32(const void* p) {
    return (uint32_t)__cvta_generic_to_shared(p);
}
__device__ __forceinline__ void ldsm4(uint32_t& a0, uint32_t& a1, uint32_t& a2, uint32_t& a3, uint32_t addr) {
    asm volatile("ldmatrix.sync.aligned.m8n8.x4.shared.b16 {%0,%1,%2,%3},[%4];"
                 : "=r"(a0), "=r"(a1), "=r"(a2), "=r"(a3) : "r"(addr));
}
__device__ __forceinline__ void mma16816(float* c, const uint32_t* a, const uint32_t* b) {
    asm volatile("mma.sync.aligned.m16n8k16.row.col.f32.f16.f16.f32 "
                 "{%0,%1,%2,%3},{%4,%5,%6,%7},{%8,%9},{%0,%1,%2,%3};"
                 : "+f"(c[0]), "+f"(c[1]), "+f"(c[2]), "+f"(c[3])
                 : "r"(a[0]), "r"(a[1]), "r"(a[2]), "r"(a[3]), "r"(b[0]), "r"(b[1]));
}
__device__ __forceinline__ u64 ffma2(u64 a, u64 b, u64 c) {
    u64 d; asm("fma.rn.f32x2 %0,%1,%2,%3;" : "=l"(d) : "l"(a), "l"(b), "l"(c)); return d;
}
__device__ __forceinline__ u64 fmul2(u64 a, u64 b) {
    u64 d; asm("mul.rn.f32x2 %0,%1,%2;" : "=l"(d) : "l"(a), "l"(b)); return d;
}
__device__ __forceinline__ u64 pack2(float x, float y) {
    u64 d; asm("mov.b64 %0,{%1,%2};" : "=l"(d) : "f"(x), "f"(y)); return d;
}
__device__ __forceinline__ float2 unpack2(u64 a) {
    float x, y; asm("mov.b64 {%0,%1},%2;" : "=f"(x), "=f"(y) : "l"(a)); return make_float2(x, y);
}
__device__ __forceinline__ void cpa4(uint32_t dst, const void* src) {
    asm volatile("cp.async.ca.shared.global [%0], [%1], 4;" :: "r"(dst), "l"(src));
}
__device__ __forceinline__ void cpa_commit() { asm volatile("cp.async.commit_group;"); }
template<int NN> __device__ __forceinline__ void cpa_wait() { asm volatile("cp.async.wait_group %0;" :: "n"(NN)); }

// ---- mbarrier / TMA ----
#define MBARRIER_INIT(addr, cnt) \
    asm volatile("mbarrier.init.shared.b64 [%0], %1;" :: "r"((uint32_t)(addr)), "r"((uint32_t)(cnt)) : "memory")
#define MBARRIER_EXPECT_TX(addr, bytes) \
    asm volatile("mbarrier.arrive.expect_tx.shared.b64 _, [%0], %1;" :: "r"((uint32_t)(addr)), "r"((uint32_t)(bytes)) : "memory")
#define TMA2D(dst, map, cx, cy, mbar) \
    asm volatile("cp.async.bulk.tensor.2d.shared::cta.global.tile.mbarrier::complete_tx::bytes [%0],[%1,{%2,%3}],[%4];" \
        :: "r"((uint32_t)(dst)), "l"(map), "r"((int)(cx)), "r"((int)(cy)), "r"((uint32_t)(mbar)) : "memory")

__device__ __forceinline__ void mbar_wait(uint32_t addr, int phase) {
    asm volatile(
        "{\n\t.reg .pred P1;\n\t"
        "WAIT_LOOP_%=:\n\t"
        "mbarrier.try_wait.parity.shared.b64 P1, [%0], %1, 0x989680;\n\t"
        "@P1 bra.uni WAIT_DONE_%=;\n\t"
        "bra.uni WAIT_LOOP_%=;\n\t"
        "WAIT_DONE_%=:\n\t}"
        :: "r"(addr), "r"((uint32_t)phase) : "memory");
}

// ---------------- transpose + split: W[K,N] fp32 -> pool[N,K] fp16 hi/lo ----------------
struct TJobs { const float* src[10]; int dstoff[10]; int K[10]; int N[10]; int tbase[11]; };

__global__ void tsplit_kernel(TJobs jb, f16* __restrict__ hi, f16* __restrict__ lo)
{
    __shared__ float s[32][33];
    int bid = blockIdx.x;
    int j = 0;
#pragma unroll
    for (int q = 1; q < 10; q++) if (bid >= jb.tbase[q]) j = q;
    int tl = bid - jb.tbase[j];
    int K = jb.K[j], N = jb.N[j];
    int ntn = N >> 5;
    int tn = tl % ntn, tk = tl / ntn;
    const float* src = jb.src[j];
    int tx = threadIdx.x, ty = threadIdx.y;   // 32 x 8
#pragma unroll
    for (int i = 0; i < 4; i++) {
        int r = tk*32 + ty + i*8, c = tn*32 + tx;
        s[ty + i*8][tx] = src[(size_t)r * N + c];
    }
    __syncthreads();
#pragma unroll
    for (int i = 0; i < 4; i++) {
        int n = tn*32 + ty + i*8, k = tk*32 + tx;
        float v = s[tx][ty + i*8];
        f16 h = __float2half_rn(v);
        size_t di = (size_t)jb.dstoff[j] + (size_t)n * K + k;
        hi[di] = h;
        lo[di] = __float2half_rn(v - __half2float(h));
    }
}

// ---------------- token shift + 6-way mix, emitting fp16 ----------------
__global__ void mix_kernel(const float* __restrict__ x,
                           const float* __restrict__ mr, const float* __restrict__ mw,
                           const float* __restrict__ mk, const float* __restrict__ mv,
                           const float* __restrict__ ma, const float* __restrict__ mg,
                           f16* __restrict__ xo)
{
    int idx = blockIdx.x * blockDim.x + threadIdx.x;     // float4 index
    const int total = BTz * Cz / 4;
    if (idx >= total) return;
    int c4 = idx % (Cz / 4);
    int bt = idx / (Cz / 4);
    int t  = bt % Tz;
    const float4* x4 = (const float4*)x;
    float4 cur = x4[idx];
    float4 prev = make_float4(0.f, 0.f, 0.f, 0.f);
    if (t > 0) prev = x4[idx - Cz / 4];
    float4 xx = make_float4(prev.x - cur.x, prev.y - cur.y, prev.z - cur.z, prev.w - cur.w);
    int c = c4 * 4;
    const float* ms[6] = { mr, mw, mk, mv, ma, mg };
#pragma unroll
    for (int s = 0; s < 6; s++) {
        float4 mm = *(const float4*)(ms[s] + c);
        f162 h0 = __floats2half2_rn(cur.x + xx.x * mm.x, cur.y + xx.y * mm.y);
        f162 h1 = __floats2half2_rn(cur.z + xx.z * mm.z, cur.w + xx.w * mm.w);
        uint2 h; h.x = *(uint32_t*)&h0; h.y = *(uint32_t*)&h1;
        ((uint2*)(xo + (size_t)s * BTz * Cz))[idx] = h;
    }
}

// ---------------- epilogue ----------------
__device__ __forceinline__ float apply_epi_rt(float acc, float b, int epi)
{
    float pre = acc + b;
    if (epi == 0) return pre;
    if (epi == 1) return tanhf(pre);
    if (epi == 2) return 1.f / (1.f + expf(-pre));
    float sp = (pre > -30.f) ? log1pf(expf(-pre)) : -pre;   // softplus(-pre)
    return expf(-expf(-sp - 0.5f));
}

// ---------------- 6-job TMA + mma.sync GEMM: C = A*Bh + A*Bl ----------------
struct G6 {
    CUtensorMap A[6], Bh[6], Bl[6];
    int K[6];
    float* C[6];
    const float* bias[6];
    int epi[6];
};

template<int BN>
__global__ __launch_bounds__(256, 2)
void tc_gemm6(const __grid_constant__ G6 jobs, int ldc)
{
    constexpr int BM = 128;
    constexpr int ATILE = BM*128;
    constexpr int BTILE = BN*128;
    constexpr int STAGE = ATILE + 2*BTILE;
    constexpr int NSTG = 2;
    constexpr int WM = 64;
    constexpr int WN = 32;
    constexpr int MFR = WM/16, NFR = WN/8;

    const int z = blockIdx.z;
    const CUtensorMap* pA  = &jobs.A[z];
    const CUtensorMap* pBh = &jobs.Bh[z];
    const CUtensorMap* pBl = &jobs.Bl[z];
    const int K   = jobs.K[z];
    float* C      = jobs.C[z];
    const float* bias = jobs.bias[z];
    const int epi = jobs.epi[z];

    extern __shared__ __align__(1024) char dsm[];
    uint32_t raw  = su32(dsm);
    uint32_t ctrl = (raw + 1023u) & ~1023u;
    uint32_t tiles = ctrl + 1024;

    const int tid = threadIdx.x, lane = tid & 31, warp = tid >> 5;
    const int wN = warp % (BN/WN), wM = warp / (BN/WN);
    const int row0 = blockIdx.y * BM, col0 = blockIdx.x * BN;
    const int T = K >> 6;

    if (tid == 0) {
#pragma unroll
        for (int s = 0; s < NSTG; s++) MBARRIER_INIT(ctrl + 16 + 8*s, 1);
    }
    __syncthreads();

    float acc[MFR][NFR][4];
#pragma unroll
    for (int i = 0; i < MFR; i++)
#pragma unroll
        for (int j = 0; j < NFR; j++)
#pragma unroll
            for (int q = 0; q < 4; q++) acc[i][j][q] = 0.f;

    const uint32_t swm = (uint32_t)((lane & 7) << 4);
    uint32_t aRow[MFR], bRow[NFR/2];
#pragma unroll
    for (int fm = 0; fm < MFR; fm++)
        aRow[fm] = (uint32_t)((wM*WM + fm*16 + (lane & 15)) * 128);
#pragma unroll
    for (int p = 0; p < NFR/2; p++)
        bRow[p] = (uint32_t)((wN*WN + p*16 + (lane & 7) + ((lane >> 4) << 3)) * 128);
    const uint32_t aColB = (uint32_t)((lane >> 4) * 16);
    const uint32_t bColB = (uint32_t)(((lane >> 3) & 1) * 16);

    auto issue_stage = [&](int s, int k0) {
        uint32_t sb = tiles + s*STAGE;
        uint32_t fb = ctrl + 16 + 8*s;
        MBARRIER_EXPECT_TX(fb, (uint32_t)STAGE);
        TMA2D(sb,             pA,  k0, row0, fb);
        TMA2D(sb+ATILE,       pBh, k0, col0, fb);
        TMA2D(sb+ATILE+BTILE, pBl, k0, col0, fb);
    };

    if (tid == 0) {
        const int npre = (T < NSTG) ? T : NSTG;
        for (int s = 0; s < npre; s++) issue_stage(s, s*64);
    }

    int ph[NSTG];
#pragma unroll
    for (int s = 0; s < NSTG; s++) ph[s] = 0;

    for (int t = 0; t < T; t++) {
        const int s = t & (NSTG-1);
        mbar_wait(ctrl + 16 + 8*s, ph[s]);
        ph[s] ^= 1;
        const uint32_t aB = tiles + s*STAGE;
        const uint32_t bH = aB + ATILE;
        const uint32_t bL = bH + BTILE;
#pragma unroll
        for (int kk = 0; kk < 4; kk++) {
            const uint32_t aC = (uint32_t)(kk*32) + aColB;
            const uint32_t bC = (uint32_t)(kk*32) + bColB;
            uint32_t Af[MFR][4], Bfh[NFR][2], Bfl[NFR][2];
#pragma unroll
            for (int fm = 0; fm < MFR; fm++) {
                uint32_t off = aRow[fm] + (aC ^ swm);
                ldsm4(Af[fm][0], Af[fm][1], Af[fm][2], Af[fm][3], aB + off);
            }
#pragma unroll
            for (int p = 0; p < NFR/2; p++) {
                uint32_t off = bRow[p] + (bC ^ swm);
                uint32_t t0, t1, t2, t3;
                ldsm4(t0, t1, t2, t3, bH + off);
                Bfh[2*p][0] = t0; Bfh[2*p][1] = t1; Bfh[2*p+1][0] = t2; Bfh[2*p+1][1] = t3;
                ldsm4(t0, t1, t2, t3, bL + off);
                Bfl[2*p][0] = t0; Bfl[2*p][1] = t1; Bfl[2*p+1][0] = t2; Bfl[2*p+1][1] = t3;
            }
#pragma unroll
            for (int fm = 0; fm < MFR; fm++)
#pragma unroll
                for (int fn = 0; fn < NFR; fn++) {
                    mma16816(acc[fm][fn], Af[fm], Bfh[fn]);
                    mma16816(acc[fm][fn], Af[fm], Bfl[fn]);
                }
        }
        __syncthreads();
        if (tid == 0 && t + NSTG < T) issue_stage(s, (t + NSTG) * 64);
    }

    // epilogue
#pragma unroll
    for (int fm = 0; fm < MFR; fm++) {
        int r = row0 + wM*WM + fm*16 + (lane >> 2);
#pragma unroll
        for (int fn = 0; fn < NFR; fn++) {
            int c = col0 + wN*WN + fn*8 + 2*(lane & 3);
            float b0 = bias ? bias[c] : 0.f;
            float b1 = bias ? bias[c+1] : 0.f;
            float x0 = apply_epi_rt(acc[fm][fn][0], b0, epi);
            float x1 = apply_epi_rt(acc[fm][fn][1], b1, epi);
            float x2 = apply_epi_rt(acc[fm][fn][2], b0, epi);
            float x3 = apply_epi_rt(acc[fm][fn][3], b1, epi);
            *(float2*)&C[(size_t)r*ldc + c]     = make_float2(x0, x1);
            *(float2*)&C[(size_t)(r+8)*ldc + c] = make_float2(x2, x3);
        }
    }
}

// ---------------- 3-job LoRA stage-1 GEMM (BN=64, fp16 out) ----------------
template<int BN>
__global__ __launch_bounds__(256, 2)
void tc_gemm3h(const __grid_constant__ CUtensorMap mA0,
               const __grid_constant__ CUtensorMap mA1,
               const __grid_constant__ CUtensorMap mA2,
               const __grid_constant__ CUtensorMap mB0h,
               const __grid_constant__ CUtensorMap mB1h,
               const __grid_constant__ CUtensorMap mB2h,
               const __grid_constant__ CUtensorMap mB0l,
               const __grid_constant__ CUtensorMap mB1l,
               const __grid_constant__ CUtensorMap mB2l,
               f16* H0, f16* H1, f16* H2,
               int ldc, int epi0, int epi1, int epi2,
               int xc0, int xc1, int xc2)
{
    constexpr int BM = 128;
    constexpr int ATILE = BM*128;
    constexpr int BTILE = BN*128;
    constexpr int STAGE = ATILE + 2*BTILE;
    constexpr int NSTG = 2;
    constexpr int WM = 32, WN = 32;
    constexpr int MFR = WM/16, NFR = WN/8;

    const int z = blockIdx.z;
    const int xcnt = (z == 0) ? xc0 : (z == 1) ? xc1 : xc2;
    if ((int)blockIdx.x >= xcnt) return;

    const CUtensorMap* pA  = (z == 0) ? &mA0  : (z == 1) ? &mA1  : &mA2;
    const CUtensorMap* pBh = (z == 0) ? &mB0h : (z == 1) ? &mB1h : &mB2h;
    const CUtensorMap* pBl = (z == 0) ? &mB0l : (z == 1) ? &mB1l : &mB2l;
    f16* Ch = (z == 0) ? H0 : (z == 1) ? H1 : H2;
    const int epi = (z == 0) ? epi0 : (z == 1) ? epi1 : epi2;
    const int K = Cz;

    extern __shared__ __align__(1024) char dsm[];
    uint32_t raw  = su32(dsm);
    uint32_t ctrl = (raw + 1023u) & ~1023u;
    uint32_t tiles = ctrl + 1024;

    const int tid = threadIdx.x, lane = tid & 31, warp = tid >> 5;
    const int wN = warp % (BN/WN), wM = warp / (BN/WN);
    const int row0 = blockIdx.y * BM, col0 = blockIdx.x * BN;
    const int T = K >> 6;

    if (tid == 0) {
#pragma unroll
        for (int s = 0; s < NSTG; s++) MBARRIER_INIT(ctrl + 16 + 8*s, 1);
    }
    __syncthreads();

    float acc[MFR][NFR][4];
#pragma unroll
    for (int i = 0; i < MFR; i++)
#pragma unroll
        for (int j = 0; j < NFR; j++)
#pragma unroll
            for (int q = 0; q < 4; q++) acc[i][j][q] = 0.f;

    const uint32_t swm = (uint32_t)((lane & 7) << 4);
    uint32_t aRow[MFR], bRow[NFR/2];
#pragma unroll
    for (int fm = 0; fm < MFR; fm++)
        aRow[fm] = (uint32_t)((wM*WM + fm*16 + (lane & 15)) * 128);
#pragma unroll
    for (int p = 0; p < NFR/2; p++)
        bRow[p] = (uint32_t)((wN*WN + p*16 + (lane & 7) + ((lane >> 4) << 3)) * 128);
    const uint32_t aColB = (uint32_t)((lane >> 4) * 16);
    const uint32_t bColB = (uint32_t)(((lane >> 3) & 1) * 16);

    auto issue_stage = [&](int s, int k0) {
        uint32_t sb = tiles + s*STAGE;
        uint32_t fb = ctrl + 16 + 8*s;
        MBARRIER_EXPECT_TX(fb, (uint32_t)STAGE);
        TMA2D(sb,             pA,  k0, row0, fb);
        TMA2D(sb+ATILE,       pBh, k0, col0, fb);
        TMA2D(sb+ATILE+BTILE, pBl, k0, col0, fb);
    };

    if (tid == 0) { issue_stage(0, 0); if (T > 1) issue_stage(1, 64); }

    int ph[NSTG] = {0, 0};

    for (int t = 0; t < T; t++) {
        const int s = t & (NSTG-1);
        mbar_wait(ctrl + 16 + 8*s, ph[s]);
        ph[s] ^= 1;
        const uint32_t aB = tiles + s*STAGE;
        const uint32_t bH = aB + ATILE;
        const uint32_t bL = bH + BTILE;
#pragma unroll
        for (int kk = 0; kk < 4; kk++) {
            const uint32_t aC = (uint32_t)(kk*32) + aColB;
            const uint32_t bC = (uint32_t)(kk*32) + bColB;
            uint32_t Af[MFR][4], Bfh[NFR][2], Bfl[NFR][2];
#pragma unroll
            for (int fm = 0; fm < MFR; fm++) {
                uint32_t off = aRow[fm] + (aC ^ swm);
                ldsm4(Af[fm][0], Af[fm][1], Af[fm][2], Af[fm][3], aB + off);
            }
#pragma unroll
            for (int p = 0; p < NFR/2; p++) {
                uint32_t off = bRow[p] + (bC ^ swm);
                uint32_t t0, t1, t2, t3;
                ldsm4(t0, t1, t2, t3, bH + off);
                Bfh[2*p][0] = t0; Bfh[2*p][1] = t1; Bfh[2*p+1][0] = t2; Bfh[2*p+1][1] = t3;
                ldsm4(t0, t1, t2, t3, bL + off);
                Bfl[2*p][0] = t0; Bfl[2*p][1] = t1; Bfl[2*p+1][0] = t2; Bfl[2*p+1][1] = t3;
            }
#pragma unroll
            for (int fm = 0; fm < MFR; fm++)
#pragma unroll
                for (int fn = 0; fn < NFR; fn++) {
                    mma16816(acc[fm][fn], Af[fm], Bfh[fn]);
                    mma16816(acc[fm][fn], Af[fm], Bfl[fn]);
                }
        }
        __syncthreads();
        if (tid == 0 && t + NSTG < T) issue_stage(s, (t + NSTG) * 64);
    }

#pragma unroll
    for (int fm = 0; fm < MFR; fm++) {
        int r = row0 + wM*WM + fm*16 + (lane >> 2);
#pragma unroll
        for (int fn = 0; fn < NFR; fn++) {
            int c = col0 + wN*WN + fn*8 + 2*(lane & 3);
            float x0 = apply_epi_rt(acc[fm][fn][0], 0.f, epi);
            float x1 = apply_epi_rt(acc[fm][fn][1], 0.f, epi);
            float x2 = apply_epi_rt(acc[fm][fn][2], 0.f, epi);
            float x3 = apply_epi_rt(acc[fm][fn][3], 0.f, epi);
            f162 h0 = __floats2half2_rn(x0, x1);
            f162 h1 = __floats2half2_rn(x2, x3);
            *(f162*)&Ch[(size_t)r*ldc + c]     = h0;
            *(f162*)&Ch[(size_t)(r+8)*ldc + c] = h1;
        }
    }
}

// ---------------- fused prep + sequential scan ----------------
// Phase 1: per-(b,h) kk-normalize / aa / bb / k-update (writes global slices).
// Phase 2: 4-buffer cp.async distance-3 prefetch scan.
__global__ __launch_bounds__(256)
void scan_kernel(const float* __restrict__ r, const float* __restrict__ wdec,
                 float* __restrict__ k, const float* __restrict__ a,
                 float* __restrict__ aaB, float* __restrict__ bbB,
                 const float* __restrict__ v, float* __restrict__ o,
                 const float* __restrict__ kkw, const float* __restrict__ kaw)
{
    const int bh = blockIdx.x;
    const int b = bh / Hz, h = bh % Hz;
    const int tid = threadIdx.x;
    const int lane = tid & 31, warp = tid >> 5;
    const size_t base = (size_t)b * Tz * Cz + h * 64;

    // ---- phase 1: prep for this (b,h) slice ----
    {
        const int gc0 = h * 64 + lane, gc1 = gc0 + 32;
        const float kk0w = kkw[gc0], kk1w = kkw[gc1];
        const float ka0 = kaw[gc0], ka1 = kaw[gc1];
        for (int t = warp; t < Tz; t += 8) {
            size_t row = base + (size_t)t * Cz;
            float k0 = k[row + lane], k1 = k[row + lane + 32];
            float kk0 = k0 * kk0w, kk1 = k1 * kk1w;
            float ss = kk0*kk0 + kk1*kk1;
#pragma unroll
            for (int m = 16; m > 0; m >>= 1) ss += __shfl_xor_sync(0xffffffffu, ss, m);
            float inv = 1.f / fmaxf(sqrtf(ss), 1e-12f);
            float a0 = a[row + lane], a1v = a[row + lane + 32];
            kk0 *= inv; kk1 *= inv;
            aaB[row + lane]      = -kk0;       aaB[row + lane + 32] = -kk1;
            bbB[row + lane]      = kk0 * a0;   bbB[row + lane + 32] = kk1 * a1v;
            k[row + lane]        = k0 * (1.f + (a0  - 1.f) * ka0);
            k[row + lane + 32]   = k1 * (1.f + (a1v - 1.f) * ka1);
        }
    }
    __syncthreads();

    // ---- phase 2: scan ----
    const int i  = tid >> 2;
    const int jq = tid & 3;
    const int jb = jq * 16;

    __shared__ __align__(16) float sm[4][6*64];   // r,w,k,aa,bb,v @ stride 64
    u64 S2[8];
#pragma unroll
    for (int q = 0; q < 8; q++) S2[q] = 0ULL;

    const float* vp[6] = { r + base, wdec + base, k + base, aaB + base, bbB + base, v + base };

    const float* myp[2]; int mys[2]; int nslot = (tid < 128) ? 2 : 1;
#pragma unroll
    for (int u = 0; u < 2; u++) {
        int lin = u * 256 + tid;
        if (lin >= 384) lin = 0;
        int vec = lin >> 6;
        int idx = lin & 63;
        const float* p = vp[0];
        if (vec == 1) p = vp[1]; else if (vec == 2) p = vp[2];
        else if (vec == 3) p = vp[3]; else if (vec == 4) p = vp[4];
        else if (vec == 5) p = vp[5];
        myp[u] = p + idx;
        mys[u] = lin;
    }

    // prologue: t=0,1,2 into bufs 0,1,2
    for (int s = 0; s < 3; s++) {
        for (int u = 0; u < nslot; u++) cpa4(su32(&sm[s][mys[u]]), myp[u] + (size_t)s * Cz);
        cpa_commit();
    }

    float* obase = o + base;
    int cur = 0;
    for (int t = 0; t < Tz; t++) {
        cpa_wait<2>();          // copies for step t complete
        __syncthreads();
        int nb = (cur + 3) & 3; // buffer read at t-1, now free
        if (t + 3 < Tz) {
            const size_t off = (size_t)(t + 3) * Cz;
            for (int u = 0; u < nslot; u++) cpa4(su32(&sm[nb][mys[u]]), myp[u] + off);
        }
        cpa_commit();

        const float* s_r  = &sm[cur][0];
        const float* s_w  = &sm[cur][64];
        const float* s_k  = &sm[cur][128];
        const float* s_aa = &sm[cur][192];
        const float* s_bb = &sm[cur][256];
        const float* s_v  = &sm[cur][320];

        u64 p0 = 0ULL, p1 = 0ULL;
#pragma unroll
        for (int g = 0; g < 4; g++) {
            ulonglong2 a2 = *(const ulonglong2*)&s_aa[jb + 4*g];
            p0 = ffma2(S2[2*g],   a2.x, p0);
            p1 = ffma2(S2[2*g+1], a2.y, p1);
        }
        float2 f0 = unpack2(p0), f1 = unpack2(p1);
        float sa = (f0.x + f0.y) + (f1.x + f1.y);
        sa += __shfl_xor_sync(0xffffffffu, sa, 1);
        sa += __shfl_xor_sync(0xffffffffu, sa, 2);
        const u64 sa2 = pack2(sa, sa);
        const float vi = s_v[i];
        const u64 vi2 = pack2(vi, vi);

        u64 o0 = 0ULL, o1 = 0ULL;
#pragma unroll
        for (int g = 0; g < 4; g++) {
            ulonglong2 w2 = *(const ulonglong2*)&s_w [jb + 4*g];
            ulonglong2 b2 = *(const ulonglong2*)&s_bb[jb + 4*g];
            ulonglong2 k2 = *(const ulonglong2*)&s_k [jb + 4*g];
            ulonglong2 r2 = *(const ulonglong2*)&s_r [jb + 4*g];
            S2[2*g]   = ffma2(S2[2*g],   w2.x, ffma2(sa2, b2.x, fmul2(vi2, k2.x)));
            o0        = ffma2(S2[2*g],   r2.x, o0);
            S2[2*g+1] = ffma2(S2[2*g+1], w2.y, ffma2(sa2, b2.y, fmul2(vi2, k2.y)));
            o1        = ffma2(S2[2*g+1], r2.y, o1);
        }
        float2 q0 = unpack2(o0), q1 = unpack2(o1);
        float out = (q0.x + q0.y) + (q1.x + q1.y);
        out += __shfl_xor_sync(0xffffffffu, out, 1);
        out += __shfl_xor_sync(0xffffffffu, out, 2);
        if (jq == 0) obase[(size_t)t * Cz + i] = out;

        cur = (cur + 1) & 3;
    }
}

// ---------------- groupnorm + rk bonus + gate -> fp16 ----------------
__global__ void post_kernel(const float* __restrict__ rk,
                            const float* __restrict__ gamma, const float* __restrict__ beta)
{
    int gw   = (blockIdx.x * blockDim.x + threadIdx.x) >> 5;
    int lane = threadIdx.x & 31;
    if (gw >= BTz * Hz) return;
    int bt = gw / Hz, h = gw % Hz;
    int c0 = h * 64 + lane, c1 = c0 + 32;
    size_t base = (size_t)bt * Cz;
    float o0 = g_o[base + c0], o1 = g_o[base + c1];
    float s1 = o0 + o1;
    float s2 = o0*o0 + o1*o1;
    float r0 = g_r[base + c0], r1 = g_r[base + c1];
    float k0 = g_k[base + c0], k1 = g_k[base + c1];
    float bon = r0 * k0 * rk[h * 64 + lane] + r1 * k1 * rk[h * 64 + lane + 32];
#pragma unroll
    for (int m = 16; m > 0; m >>= 1) {
        s1  += __shfl_xor_sync(0xffffffffu, s1,  m);
        s2  += __shfl_xor_sync(0xffffffffu, s2,  m);
        bon += __shfl_xor_sync(0xffffffffu, bon, m);
    }
    float mu   = s1 * (1.f / 64.f);
    float var  = s2 * (1.f / 64.f) - mu * mu;
    float rstd = rsqrtf(var + 0.00064f);
    float v0 = g_v[base + c0], v1 = g_v[base + c1];
    float y0 = ((o0 - mu) * rstd * gamma[c0] + beta[c0] + bon * v0) * g_g[base + c0];
    float y1 = ((o1 - mu) * rstd * gamma[c1] + beta[c1] + bon * v1) * g_g[base + c1];
    g_yg[base + c0] = __float2half_rn(y0);
    g_yg[base + c1] = __float2half_rn(y1);
}

// ---------------- host: tensormap builder ----------------
typedef CUresult (*PFN_encode)(CUtensorMap*, CUtensorMapDataType, cuuint32_t, void*,
                               const cuuint64_t*, const cuuint64_t*, const cuuint32_t*,
                               const cuuint32_t*, CUtensorMapInterleave, CUtensorMapSwizzle,
                               CUtensorMapL2promotion, CUtensorMapFloatOOBfill);

static void make_map(PFN_encode enc, CUtensorMap* m, const void* base,
                     unsigned long long d0, unsigned long long d1,
                     unsigned long long stride1B, unsigned box0, unsigned box1)
{
    cuuint64_t dims[2]    = { d0, d1 };
    cuuint64_t strides[1] = { stride1B };
    cuuint32_t box[2]     = { box0, box1 };
    cuuint32_t es[2]      = { 1, 1 };
    enc(m, CU_TENSOR_MAP_DATA_TYPE_FLOAT16, 2, (void*)base, dims, strides, box, es,
        CU_TENSOR_MAP_INTERLEAVE_NONE, CU_TENSOR_MAP_SWIZZLE_128B,
        CU_TENSOR_MAP_L2_PROMOTION_L2_128B, CU_TENSOR_MAP_FLOAT_OOB_FILL_NONE);
}

#define SMEM_128 (2048 + 2*(128*128 + 2*128*128))
#define SMEM_64  (2048 + 2*(128*128 + 2*64*128))

// ---------------- launch ----------------
extern "C" void kernel_launch(void* const* d_in, const int* in_sizes, int n_in,
                              void* d_out, int out_size)
{
    const float* x    = (const float*)d_in[0];
    const float* x_r  = (const float*)d_in[1];
    const float* x_w  = (const float*)d_in[2];
    const float* x_k  = (const float*)d_in[3];
    const float* x_v  = (const float*)d_in[4];
    const float* x_a  = (const float*)d_in[5];
    const float* x_g  = (const float*)d_in[6];
    const float* w0   = (const float*)d_in[7];
    const float* w1   = (const float*)d_in[8];
    const float* w2   = (const float*)d_in[9];
    const float* a0   = (const float*)d_in[10];
    const float* a1   = (const float*)d_in[11];
    const float* a2   = (const float*)d_in[12];
    const float* g1   = (const float*)d_in[16];
    const float* g2   = (const float*)d_in[17];
    const float* k_k  = (const float*)d_in[18];
    const float* k_a  = (const float*)d_in[19];
    const float* r_k  = (const float*)d_in[20];
    const float* Wr   = (const float*)d_in[21];
    const float* Wk   = (const float*)d_in[22];
    const float* Wv   = (const float*)d_in[23];
    const float* Wo   = (const float*)d_in[24];
    const float* lg   = (const float*)d_in[25];
    const float* lb   = (const float*)d_in[26];

    void *pr, *pk, *pv, *pwd, *pa, *pg, *paa, *pbb, *po;
    void *px6, *pyg, *phid, *pwh, *pwl;
    cudaGetSymbolAddress(&pr,  g_r);   cudaGetSymbolAddress(&pk,  g_k);
    cudaGetSymbolAddress(&pv,  g_v);   cudaGetSymbolAddress(&pwd, g_wd);
    cudaGetSymbolAddress(&pa,  g_a);   cudaGetSymbolAddress(&pg,  g_g);
    cudaGetSymbolAddress(&paa, g_aa);  cudaGetSymbolAddress(&pbb, g_bb);
    cudaGetSymbolAddress(&po,  g_o);
    cudaGetSymbolAddress(&px6, g_x6);  cudaGetSymbolAddress(&pyg, g_yg);
    cudaGetSymbolAddress(&phid, g_hid);
    cudaGetSymbolAddress(&pwh, g_wh);  cudaGetSymbolAddress(&pwl, g_wl);

    float *rb = (float*)pr, *kb = (float*)pk, *vb = (float*)pv, *wd = (float*)pwd;
    float *ab = (float*)pa, *gb = (float*)pg, *aab = (float*)paa, *bbb = (float*)pbb;
    float *ob = (float*)po;
    f16 *x6 = (f16*)px6, *yg = (f16*)pyg, *hid = (f16*)phid;
    f16 *wh = (f16*)pwh, *wl = (f16*)pwl;

    const size_t S = (size_t)BTz * Cz;

    cudaFuncSetAttribute(tc_gemm6<128>, cudaFuncAttributeMaxDynamicSharedMemorySize, SMEM_128);
    cudaFuncSetAttribute(tc_gemm3h<64>, cudaFuncAttributeMaxDynamicSharedMemorySize, SMEM_64);

    PFN_encode enc = nullptr;
    cudaDriverEntryPointQueryResult qres;
    cudaGetDriverEntryPoint("cuTensorMapEncodeTiled", (void**)&enc,
                            cudaEnableDefault, &qres);

    // 1. transpose+split all weights into the pool
    TJobs jb;
    jb.src[0]=Wr; jb.src[1]=Wk; jb.src[2]=Wv; jb.src[3]=Wo;
    jb.src[4]=w1; jb.src[5]=a1; jb.src[6]=g1;
    jb.src[7]=w2; jb.src[8]=a2; jb.src[9]=g2;
    jb.dstoff[0]=O_Wr; jb.dstoff[1]=O_Wk; jb.dstoff[2]=O_Wv; jb.dstoff[3]=O_Wo;
    jb.dstoff[4]=O_L1; jb.dstoff[5]=O_L1+64*Cz; jb.dstoff[6]=O_L1+128*Cz;
    jb.dstoff[7]=O_W2T; jb.dstoff[8]=O_A2T; jb.dstoff[9]=O_G2T;
    jb.K[0]=jb.K[1]=jb.K[2]=jb.K[3]=Cz; jb.K[4]=jb.K[5]=jb.K[6]=Cz;
    jb.K[7]=64; jb.K[8]=64; jb.K[9]=128;
    jb.N[0]=jb.N[1]=jb.N[2]=jb.N[3]=Cz; jb.N[4]=64; jb.N[5]=64; jb.N[6]=128;
    jb.N[7]=Cz; jb.N[8]=Cz; jb.N[9]=Cz;
    int tb = 0;
    for (int j = 0; j < 10; j++) { jb.tbase[j] = tb; tb += (jb.K[j]/32)*(jb.N[j]/32); }
    jb.tbase[10] = tb;
    tsplit_kernel<<<tb, dim3(32,8)>>>(jb, wh, wl);

    // 2. token shift + mix
    mix_kernel<<<(BTz*Cz/4 + 255)/256, 256>>>(x, x_r, x_w, x_k, x_v, x_a, x_g, x6);

    CUtensorMap A0, A1, A2, B0h, B1h, B2h, B0l, B1l, B2l;

    // 3. fused LoRA stage-1: z0 hw=tanh(xw@w1), z1 ha=xa@a1, z2 hg=sig(xg@g1)
    make_map(enc, &A0,  x6 + 1*S, Cz, BTz, Cz*2, 64, 128);
    make_map(enc, &A1,  x6 + 4*S, Cz, BTz, Cz*2, 64, 128);
    make_map(enc, &A2,  x6 + 5*S, Cz, BTz, Cz*2, 64, 128);
    make_map(enc, &B0h, wh + O_L1,          Cz, 64,  Cz*2, 64, 64);
    make_map(enc, &B1h, wh + O_L1 + 64*Cz,  Cz, 64,  Cz*2, 64, 64);
    make_map(enc, &B2h, wh + O_L1 + 128*Cz, Cz, 128, Cz*2, 64, 64);
    make_map(enc, &B0l, wl + O_L1,          Cz, 64,  Cz*2, 64, 64);
    make_map(enc, &B1l, wl + O_L1 + 64*Cz,  Cz, 64,  Cz*2, 64, 64);
    make_map(enc, &B2l, wl + O_L1 + 128*Cz, Cz, 128, Cz*2, 64, 64);
    tc_gemm3h<64><<<dim3(2, BTz/128, 3), 256, SMEM_64>>>(
        A0, A1, A2, B0h, B1h, B2h, B0l, B1l, B2l,
        hid, hid + 64, hid + 128,
        256, 1, 0, 2, 1, 1, 2);

    // 4. ONE launch: r, k, v projections + LoRA stage-2 (6 jobs)
    G6 g6;
    make_map(enc, &g6.A[0], x6 + 0*S, Cz, BTz, Cz*2, 64, 128);
    make_map(enc, &g6.A[1], x6 + 2*S, Cz, BTz, Cz*2, 64, 128);
    make_map(enc, &g6.A[2], x6 + 3*S, Cz, BTz, Cz*2, 64, 128);
    make_map(enc, &g6.A[3], hid,       64,  BTz, 256*2, 64, 128);
    make_map(enc, &g6.A[4], hid + 64,  64,  BTz, 256*2, 64, 128);
    make_map(enc, &g6.A[5], hid + 128, 128, BTz, 256*2, 64, 128);
    make_map(enc, &g6.Bh[0], wh + O_Wr,  Cz,  Cz, Cz*2,  64, 128);
    make_map(enc, &g6.Bh[1], wh + O_Wk,  Cz,  Cz, Cz*2,  64, 128);
    make_map(enc, &g6.Bh[2], wh + O_Wv,  Cz,  Cz, Cz*2,  64, 128);
    make_map(enc, &g6.Bh[3], wh + O_W2T, 64,  Cz, 64*2,  64, 128);
    make_map(enc, &g6.Bh[4], wh + O_A2T, 64,  Cz, 64*2,  64, 128);
    make_map(enc, &g6.Bh[5], wh + O_G2T, 128, Cz, 128*2, 64, 128);
    make_map(enc, &g6.Bl[0], wl + O_Wr,  Cz,  Cz, Cz*2,  64, 128);
    make_map(enc, &g6.Bl[1], wl + O_Wk,  Cz,  Cz, Cz*2,  64, 128);
    make_map(enc, &g6.Bl[2], wl + O_Wv,  Cz,  Cz, Cz*2,  64, 128);
    make_map(enc, &g6.Bl[3], wl + O_W2T, 64,  Cz, 64*2,  64, 128);
    make_map(enc, &g6.Bl[4], wl + O_A2T, 64,  Cz, 64*2,  64, 128);
    make_map(enc, &g6.Bl[5], wl + O_G2T, 128, Cz, 128*2, 64, 128);
    g6.K[0] = Cz; g6.K[1] = Cz; g6.K[2] = Cz; g6.K[3] = 64; g6.K[4] = 64; g6.K[5] = 128;
    g6.C[0] = rb; g6.C[1] = kb; g6.C[2] = vb; g6.C[3] = wd; g6.C[4] = ab; g6.C[5] = gb;
    g6.bias[0] = nullptr; g6.bias[1] = nullptr; g6.bias[2] = nullptr;
    g6.bias[3] = w0; g6.bias[4] = a0; g6.bias[5] = nullptr;
    g6.epi[0] = 0; g6.epi[1] = 0; g6.epi[2] = 0; g6.epi[3] = 3; g6.epi[4] = 2; g6.epi[5] = 0;
    tc_gemm6<128><<<dim3(8, BTz/128, 6), 256, SMEM_128>>>(g6, Cz);

    // 5. fused prep + sequential scan
    scan_kernel<<<Bz*Hz, 256>>>(rb, wd, kb, ab, aab, bbb, vb, ob, k_k, k_a);

    // 6. groupnorm + bonus + gate -> yg fp16
    post_kernel<<<BTz*Hz/8, 256>>>(r_k, lg, lb);

    // 7. output projection (1 job)
    G6 go;
    make_map(enc, &go.A[0],  yg, Cz, BTz, Cz*2, 64, 128);
    make_map(enc, &go.Bh[0], wh + O_Wo, Cz, Cz, Cz*2, 64, 128);
    make_map(enc, &go.Bl[0], wl + O_Wo, Cz, Cz, Cz*2, 64, 128);
    for (int z = 1; z < 6; z++) { go.A[z] = go.A[0]; go.Bh[z] = go.Bh[0]; go.Bl[z] = go.Bl[0]; }
    for (int z = 0; z < 6; z++) { go.K[z] = Cz; go.C[z] = (float*)d_out; go.bias[z] = nullptr; go.epi[z] = 0; }
    tc_gemm6<128><<<dim3(8, BTz/128, 1), 256, SMEM_128>>>(go, Cz);

    // 8. v_first if expected
    if (out_size >= 2 * BTz * Cz) {
        cudaMemcpyAsync((float*)d_out + S, vb, sizeof(float) * S, cudaMemcpyDeviceToDevice);
    }
}

// round 15
// speedup vs baseline: 1.2126x; 1.2126x over previous
#include <cuda_runtime.h>
#include <cuda.h>
#include <cuda_bf16.h>
#include <cuda_fp16.h>
#include <cstdint>
#include <math.h>

#define Bz   4
#define Tz   1024
#define Cz   1024
#define Hz   16
#define BTz  (Bz*Tz)

typedef __half  f16;
typedef __half2 f162;
typedef unsigned long long u64;

// ---------------- scratch (device globals; no allocation allowed) ----------------
__device__ float g_r [BTz*Cz], g_k [BTz*Cz], g_v [BTz*Cz], g_wd[BTz*Cz];
__device__ float g_a [BTz*Cz], g_g [BTz*Cz], g_aa[BTz*Cz], g_bb[BTz*Cz], g_o [BTz*Cz];

__device__ __align__(256) f16 g_x6[6*BTz*Cz];     // mixed streams, fp16
__device__ __align__(256) f16 g_yg[BTz*Cz];       // (gn(o)+bonus)*g fp16
// LoRA hidden pool [BTz, 256]: cols 0-63 decay, 64-127 a, 128-255 g (fp16)
__device__ __align__(256) f16 g_hid[BTz*256];

// weight pool: all matrices stored TRANSPOSED [N, K] row-major, fp16 hi/lo
#define O_Wr 0
#define O_Wk (Cz*Cz)
#define O_Wv (2*Cz*Cz)
#define O_Wo (3*Cz*Cz)
#define O_L1 (4*Cz*Cz)                  // [256, 1024]: w1t 0-63, a1t 64-127, g1t 128-255
#define O_W2T (O_L1 + 256*Cz)           // [1024, 64]
#define O_A2T (O_W2T + Cz*64)           // [1024, 64]
#define O_G2T (O_A2T + Cz*64)           // [1024, 128]
#define WPOOL (O_G2T + Cz*128)
__device__ __align__(256) f16 g_wh[WPOOL], g_wl[WPOOL];

// ---------------- helpers ----------------
__device__ __forceinline__ uint32_t su32(const void* p) {
    return (uint32_t)__cvta_generic_to_shared(p);
}
__device__ __forceinline__ void ldsm4(uint32_t& a0, uint32_t& a1, uint32_t& a2, uint32_t& a3, uint32_t addr) {
    asm volatile("ldmatrix.sync.aligned.m8n8.x4.shared.b16 {%0,%1,%2,%3},[%4];"
                 : "=r"(a0), "=r"(a1), "=r"(a2), "=r"(a3) : "r"(addr));
}
__device__ __forceinline__ void mma16816(float* c, const uint32_t* a, const uint32_t* b) {
    asm volatile("mma.sync.aligned.m16n8k16.row.col.f32.f16.f16.f32 "
                 "{%0,%1,%2,%3},{%4,%5,%6,%7},{%8,%9},{%0,%1,%2,%3};"
                 : "+f"(c[0]), "+f"(c[1]), "+f"(c[2]), "+f"(c[3])
                 : "r"(a[0]), "r"(a[1]), "r"(a[2]), "r"(a[3]), "r"(b[0]), "r"(b[1]));
}
__device__ __forceinline__ u64 ffma2(u64 a, u64 b, u64 c) {
    u64 d; asm("fma.rn.f32x2 %0,%1,%2,%3;" : "=l"(d) : "l"(a), "l"(b), "l"(c)); return d;
}
__device__ __forceinline__ u64 fmul2(u64 a, u64 b) {
    u64 d; asm("mul.rn.f32x2 %0,%1,%2;" : "=l"(d) : "l"(a), "l"(b)); return d;
}
__device__ __forceinline__ u64 pack2(float x, float y) {
    u64 d; asm("mov.b64 %0,{%1,%2};" : "=l"(d) : "f"(x), "f"(y)); return d;
}
__device__ __forceinline__ float2 unpack2(u64 a) {
    float x, y; asm("mov.b64 {%0,%1},%2;" : "=f"(x), "=f"(y) : "l"(a)); return make_float2(x, y);
}

// ---- mbarrier / TMA ----
#define MBARRIER_INIT(addr, cnt) \
    asm volatile("mbarrier.init.shared.b64 [%0], %1;" :: "r"((uint32_t)(addr)), "r"((uint32_t)(cnt)) : "memory")
#define MBARRIER_EXPECT_TX(addr, bytes) \
    asm volatile("mbarrier.arrive.expect_tx.shared.b64 _, [%0], %1;" :: "r"((uint32_t)(addr)), "r"((uint32_t)(bytes)) : "memory")
#define TMA2D(dst, map, cx, cy, mbar) \
    asm volatile("cp.async.bulk.tensor.2d.shared::cta.global.tile.mbarrier::complete_tx::bytes [%0],[%1,{%2,%3}],[%4];" \
        :: "r"((uint32_t)(dst)), "l"(map), "r"((int)(cx)), "r"((int)(cy)), "r"((uint32_t)(mbar)) : "memory")

__device__ __forceinline__ void mbar_wait(uint32_t addr, int phase) {
    asm volatile(
        "{\n\t.reg .pred P1;\n\t"
        "WAIT_LOOP_%=:\n\t"
        "mbarrier.try_wait.parity.shared.b64 P1, [%0], %1, 0x989680;\n\t"
        "@P1 bra.uni WAIT_DONE_%=;\n\t"
        "bra.uni WAIT_LOOP_%=;\n\t"
        "WAIT_DONE_%=:\n\t}"
        :: "r"(addr), "r"((uint32_t)phase) : "memory");
}

// ---------------- transpose + split: W[K,N] fp32 -> pool[N,K] fp16 hi/lo ----------------
struct TJobs { const float* src[10]; int dstoff[10]; int K[10]; int N[10]; int tbase[11]; };

__global__ void tsplit_kernel(TJobs jb, f16* __restrict__ hi, f16* __restrict__ lo)
{
    __shared__ float s[32][33];
    int bid = blockIdx.x;
    int j = 0;
#pragma unroll
    for (int q = 1; q < 10; q++) if (bid >= jb.tbase[q]) j = q;
    int tl = bid - jb.tbase[j];
    int K = jb.K[j], N = jb.N[j];
    int ntn = N >> 5;
    int tn = tl % ntn, tk = tl / ntn;
    const float* src = jb.src[j];
    int tx = threadIdx.x, ty = threadIdx.y;   // 32 x 8
#pragma unroll
    for (int i = 0; i < 4; i++) {
        int r = tk*32 + ty + i*8, c = tn*32 + tx;
        s[ty + i*8][tx] = src[(size_t)r * N + c];
    }
    __syncthreads();
#pragma unroll
    for (int i = 0; i < 4; i++) {
        int n = tn*32 + ty + i*8, k = tk*32 + tx;
        float v = s[tx][ty + i*8];
        f16 h = __float2half_rn(v);
        size_t di = (size_t)jb.dstoff[j] + (size_t)n * K + k;
        hi[di] = h;
        lo[di] = __float2half_rn(v - __half2float(h));
    }
}

// ---------------- token shift + 6-way mix, emitting fp16 ----------------
__global__ void mix_kernel(const float* __restrict__ x,
                           const float* __restrict__ mr, const float* __restrict__ mw,
                           const float* __restrict__ mk, const float* __restrict__ mv,
                           const float* __restrict__ ma, const float* __restrict__ mg,
                           f16* __restrict__ xo)
{
    int idx = blockIdx.x * blockDim.x + threadIdx.x;     // float4 index
    const int total = BTz * Cz / 4;
    if (idx >= total) return;
    int c4 = idx % (Cz / 4);
    int bt = idx / (Cz / 4);
    int t  = bt % Tz;
    const float4* x4 = (const float4*)x;
    float4 cur = x4[idx];
    float4 prev = make_float4(0.f, 0.f, 0.f, 0.f);
    if (t > 0) prev = x4[idx - Cz / 4];
    float4 xx = make_float4(prev.x - cur.x, prev.y - cur.y, prev.z - cur.z, prev.w - cur.w);
    int c = c4 * 4;
    const float* ms[6] = { mr, mw, mk, mv, ma, mg };
#pragma unroll
    for (int s = 0; s < 6; s++) {
        float4 mm = *(const float4*)(ms[s] + c);
        f162 h0 = __floats2half2_rn(cur.x + xx.x * mm.x, cur.y + xx.y * mm.y);
        f162 h1 = __floats2half2_rn(cur.z + xx.z * mm.z, cur.w + xx.w * mm.w);
        uint2 h; h.x = *(uint32_t*)&h0; h.y = *(uint32_t*)&h1;
        ((uint2*)(xo + (size_t)s * BTz * Cz))[idx] = h;
    }
}

// ---------------- epilogue ----------------
__device__ __forceinline__ float apply_epi_rt(float acc, float b, int epi)
{
    float pre = acc + b;
    if (epi == 0) return pre;
    if (epi == 1) return tanhf(pre);
    if (epi == 2) return 1.f / (1.f + expf(-pre));
    float sp = (pre > -30.f) ? log1pf(expf(-pre)) : -pre;   // softplus(-pre)
    return expf(-expf(-sp - 0.5f));
}

// ---------------- 6-job TMA + mma.sync GEMM: C = A*Bh + A*Bl ----------------
struct G6 {
    CUtensorMap A[6], Bh[6], Bl[6];
    int K[6];
    float* C[6];
    const float* bias[6];
    int epi[6];
};

template<int BN>
__global__ __launch_bounds__(256, 2)
void tc_gemm6(const __grid_constant__ G6 jobs, int ldc)
{
    constexpr int BM = 128;
    constexpr int ATILE = BM*128;
    constexpr int BTILE = BN*128;
    constexpr int STAGE = ATILE + 2*BTILE;
    constexpr int NSTG = 2;
    constexpr int WM = 64;
    constexpr int WN = 32;
    constexpr int MFR = WM/16, NFR = WN/8;

    const int z = blockIdx.z;
    const CUtensorMap* pA  = &jobs.A[z];
    const CUtensorMap* pBh = &jobs.Bh[z];
    const CUtensorMap* pBl = &jobs.Bl[z];
    const int K   = jobs.K[z];
    float* C      = jobs.C[z];
    const float* bias = jobs.bias[z];
    const int epi = jobs.epi[z];

    extern __shared__ __align__(1024) char dsm[];
    uint32_t raw  = su32(dsm);
    uint32_t ctrl = (raw + 1023u) & ~1023u;
    uint32_t tiles = ctrl + 1024;

    const int tid = threadIdx.x, lane = tid & 31, warp = tid >> 5;
    const int wN = warp % (BN/WN), wM = warp / (BN/WN);
    const int row0 = blockIdx.y * BM, col0 = blockIdx.x * BN;
    const int T = K >> 6;

    if (tid == 0) {
#pragma unroll
        for (int s = 0; s < NSTG; s++) MBARRIER_INIT(ctrl + 16 + 8*s, 1);
    }
    __syncthreads();

    float acc[MFR][NFR][4];
#pragma unroll
    for (int i = 0; i < MFR; i++)
#pragma unroll
        for (int j = 0; j < NFR; j++)
#pragma unroll
            for (int q = 0; q < 4; q++) acc[i][j][q] = 0.f;

    const uint32_t swm = (uint32_t)((lane & 7) << 4);
    uint32_t aRow[MFR], bRow[NFR/2];
#pragma unroll
    for (int fm = 0; fm < MFR; fm++)
        aRow[fm] = (uint32_t)((wM*WM + fm*16 + (lane & 15)) * 128);
#pragma unroll
    for (int p = 0; p < NFR/2; p++)
        bRow[p] = (uint32_t)((wN*WN + p*16 + (lane & 7) + ((lane >> 4) << 3)) * 128);
    const uint32_t aColB = (uint32_t)((lane >> 4) * 16);
    const uint32_t bColB = (uint32_t)(((lane >> 3) & 1) * 16);

    auto issue_stage = [&](int s, int k0) {
        uint32_t sb = tiles + s*STAGE;
        uint32_t fb = ctrl + 16 + 8*s;
        MBARRIER_EXPECT_TX(fb, (uint32_t)STAGE);
        TMA2D(sb,             pA,  k0, row0, fb);
        TMA2D(sb+ATILE,       pBh, k0, col0, fb);
        TMA2D(sb+ATILE+BTILE, pBl, k0, col0, fb);
    };

    if (tid == 0) {
        const int npre = (T < NSTG) ? T : NSTG;
        for (int s = 0; s < npre; s++) issue_stage(s, s*64);
    }

    int ph[NSTG];
#pragma unroll
    for (int s = 0; s < NSTG; s++) ph[s] = 0;

    for (int t = 0; t < T; t++) {
        const int s = t & (NSTG-1);
        mbar_wait(ctrl + 16 + 8*s, ph[s]);
        ph[s] ^= 1;
        const uint32_t aB = tiles + s*STAGE;
        const uint32_t bH = aB + ATILE;
        const uint32_t bL = bH + BTILE;
#pragma unroll
        for (int kk = 0; kk < 4; kk++) {
            const uint32_t aC = (uint32_t)(kk*32) + aColB;
            const uint32_t bC = (uint32_t)(kk*32) + bColB;
            uint32_t Af[MFR][4], Bfh[NFR][2], Bfl[NFR][2];
#pragma unroll
            for (int fm = 0; fm < MFR; fm++) {
                uint32_t off = aRow[fm] + (aC ^ swm);
                ldsm4(Af[fm][0], Af[fm][1], Af[fm][2], Af[fm][3], aB + off);
            }
#pragma unroll
            for (int p = 0; p < NFR/2; p++) {
                uint32_t off = bRow[p] + (bC ^ swm);
                uint32_t t0, t1, t2, t3;
                ldsm4(t0, t1, t2, t3, bH + off);
                Bfh[2*p][0] = t0; Bfh[2*p][1] = t1; Bfh[2*p+1][0] = t2; Bfh[2*p+1][1] = t3;
                ldsm4(t0, t1, t2, t3, bL + off);
                Bfl[2*p][0] = t0; Bfl[2*p][1] = t1; Bfl[2*p+1][0] = t2; Bfl[2*p+1][1] = t3;
            }
#pragma unroll
            for (int fm = 0; fm < MFR; fm++)
#pragma unroll
                for (int fn = 0; fn < NFR; fn++) {
                    mma16816(acc[fm][fn], Af[fm], Bfh[fn]);
                    mma16816(acc[fm][fn], Af[fm], Bfl[fn]);
                }
        }
        __syncthreads();
        if (tid == 0 && t + NSTG < T) issue_stage(s, (t + NSTG) * 64);
    }

    // epilogue
#pragma unroll
    for (int fm = 0; fm < MFR; fm++) {
        int r = row0 + wM*WM + fm*16 + (lane >> 2);
#pragma unroll
        for (int fn = 0; fn < NFR; fn++) {
            int c = col0 + wN*WN + fn*8 + 2*(lane & 3);
            float b0 = bias ? bias[c] : 0.f;
            float b1 = bias ? bias[c+1] : 0.f;
            float x0 = apply_epi_rt(acc[fm][fn][0], b0, epi);
            float x1 = apply_epi_rt(acc[fm][fn][1], b1, epi);
            float x2 = apply_epi_rt(acc[fm][fn][2], b0, epi);
            float x3 = apply_epi_rt(acc[fm][fn][3], b1, epi);
            *(float2*)&C[(size_t)r*ldc + c]     = make_float2(x0, x1);
            *(float2*)&C[(size_t)(r+8)*ldc + c] = make_float2(x2, x3);
        }
    }
}

// ---------------- 3-job LoRA stage-1 GEMM (BN=64, fp16 out) ----------------
template<int BN>
__global__ __launch_bounds__(256, 2)
void tc_gemm3h(const __grid_constant__ CUtensorMap mA0,
               const __grid_constant__ CUtensorMap mA1,
               const __grid_constant__ CUtensorMap mA2,
               const __grid_constant__ CUtensorMap mB0h,
               const __grid_constant__ CUtensorMap mB1h,
               const __grid_constant__ CUtensorMap mB2h,
               const __grid_constant__ CUtensorMap mB0l,
               const __grid_constant__ CUtensorMap mB1l,
               const __grid_constant__ CUtensorMap mB2l,
               f16* H0, f16* H1, f16* H2,
               int ldc, int epi0, int epi1, int epi2,
               int xc0, int xc1, int xc2)
{
    constexpr int BM = 128;
    constexpr int ATILE = BM*128;
    constexpr int BTILE = BN*128;
    constexpr int STAGE = ATILE + 2*BTILE;
    constexpr int NSTG = 2;
    constexpr int WM = 32, WN = 32;
    constexpr int MFR = WM/16, NFR = WN/8;

    const int z = blockIdx.z;
    const int xcnt = (z == 0) ? xc0 : (z == 1) ? xc1 : xc2;
    if ((int)blockIdx.x >= xcnt) return;

    const CUtensorMap* pA  = (z == 0) ? &mA0  : (z == 1) ? &mA1  : &mA2;
    const CUtensorMap* pBh = (z == 0) ? &mB0h : (z == 1) ? &mB1h : &mB2h;
    const CUtensorMap* pBl = (z == 0) ? &mB0l : (z == 1) ? &mB1l : &mB2l;
    f16* Ch = (z == 0) ? H0 : (z == 1) ? H1 : H2;
    const int epi = (z == 0) ? epi0 : (z == 1) ? epi1 : epi2;
    const int K = Cz;

    extern __shared__ __align__(1024) char dsm[];
    uint32_t raw  = su32(dsm);
    uint32_t ctrl = (raw + 1023u) & ~1023u;
    uint32_t tiles = ctrl + 1024;

    const int tid = threadIdx.x, lane = tid & 31, warp = tid >> 5;
    const int wN = warp % (BN/WN), wM = warp / (BN/WN);
    const int row0 = blockIdx.y * BM, col0 = blockIdx.x * BN;
    const int T = K >> 6;

    if (tid == 0) {
#pragma unroll
        for (int s = 0; s < NSTG; s++) MBARRIER_INIT(ctrl + 16 + 8*s, 1);
    }
    __syncthreads();

    float acc[MFR][NFR][4];
#pragma unroll
    for (int i = 0; i < MFR; i++)
#pragma unroll
        for (int j = 0; j < NFR; j++)
#pragma unroll
            for (int q = 0; q < 4; q++) acc[i][j][q] = 0.f;

    const uint32_t swm = (uint32_t)((lane & 7) << 4);
    uint32_t aRow[MFR], bRow[NFR/2];
#pragma unroll
    for (int fm = 0; fm < MFR; fm++)
        aRow[fm] = (uint32_t)((wM*WM + fm*16 + (lane & 15)) * 128);
#pragma unroll
    for (int p = 0; p < NFR/2; p++)
        bRow[p] = (uint32_t)((wN*WN + p*16 + (lane & 7) + ((lane >> 4) << 3)) * 128);
    const uint32_t aColB = (uint32_t)((lane >> 4) * 16);
    const uint32_t bColB = (uint32_t)(((lane >> 3) & 1) * 16);

    auto issue_stage = [&](int s, int k0) {
        uint32_t sb = tiles + s*STAGE;
        uint32_t fb = ctrl + 16 + 8*s;
        MBARRIER_EXPECT_TX(fb, (uint32_t)STAGE);
        TMA2D(sb,             pA,  k0, row0, fb);
        TMA2D(sb+ATILE,       pBh, k0, col0, fb);
        TMA2D(sb+ATILE+BTILE, pBl, k0, col0, fb);
    };

    if (tid == 0) { issue_stage(0, 0); if (T > 1) issue_stage(1, 64); }

    int ph[NSTG] = {0, 0};

    for (int t = 0; t < T; t++) {
        const int s = t & (NSTG-1);
        mbar_wait(ctrl + 16 + 8*s, ph[s]);
        ph[s] ^= 1;
        const uint32_t aB = tiles + s*STAGE;
        const uint32_t bH = aB + ATILE;
        const uint32_t bL = bH + BTILE;
#pragma unroll
        for (int kk = 0; kk < 4; kk++) {
            const uint32_t aC = (uint32_t)(kk*32) + aColB;
            const uint32_t bC = (uint32_t)(kk*32) + bColB;
            uint32_t Af[MFR][4], Bfh[NFR][2], Bfl[NFR][2];
#pragma unroll
            for (int fm = 0; fm < MFR; fm++) {
                uint32_t off = aRow[fm] + (aC ^ swm);
                ldsm4(Af[fm][0], Af[fm][1], Af[fm][2], Af[fm][3], aB + off);
            }
#pragma unroll
            for (int p = 0; p < NFR/2; p++) {
                uint32_t off = bRow[p] + (bC ^ swm);
                uint32_t t0, t1, t2, t3;
                ldsm4(t0, t1, t2, t3, bH + off);
                Bfh[2*p][0] = t0; Bfh[2*p][1] = t1; Bfh[2*p+1][0] = t2; Bfh[2*p+1][1] = t3;
                ldsm4(t0, t1, t2, t3, bL + off);
                Bfl[2*p][0] = t0; Bfl[2*p][1] = t1; Bfl[2*p+1][0] = t2; Bfl[2*p+1][1] = t3;
            }
#pragma unroll
            for (int fm = 0; fm < MFR; fm++)
#pragma unroll
                for (int fn = 0; fn < NFR; fn++) {
                    mma16816(acc[fm][fn], Af[fm], Bfh[fn]);
                    mma16816(acc[fm][fn], Af[fm], Bfl[fn]);
                }
        }
        __syncthreads();
        if (tid == 0 && t + NSTG < T) issue_stage(s, (t + NSTG) * 64);
    }

#pragma unroll
    for (int fm = 0; fm < MFR; fm++) {
        int r = row0 + wM*WM + fm*16 + (lane >> 2);
#pragma unroll
        for (int fn = 0; fn < NFR; fn++) {
            int c = col0 + wN*WN + fn*8 + 2*(lane & 3);
            float x0 = apply_epi_rt(acc[fm][fn][0], 0.f, epi);
            float x1 = apply_epi_rt(acc[fm][fn][1], 0.f, epi);
            float x2 = apply_epi_rt(acc[fm][fn][2], 0.f, epi);
            float x3 = apply_epi_rt(acc[fm][fn][3], 0.f, epi);
            f162 h0 = __floats2half2_rn(x0, x1);
            f162 h1 = __floats2half2_rn(x2, x3);
            *(f162*)&Ch[(size_t)r*ldc + c]     = h0;
            *(f162*)&Ch[(size_t)(r+8)*ldc + c] = h1;
        }
    }
}

// ---------------- kk normalize, aa, bb, k update (parallel) ----------------
__global__ void prep_kernel(const float* __restrict__ kkw, const float* __restrict__ kaw)
{
    int gw   = (blockIdx.x * blockDim.x + threadIdx.x) >> 5;
    int lane = threadIdx.x & 31;
    if (gw >= BTz * Hz) return;
    int bt = gw / Hz, h = gw % Hz;
    int c0 = h * 64 + lane, c1 = c0 + 32;
    size_t base = (size_t)bt * Cz;
    float k0 = g_k[base + c0], k1 = g_k[base + c1];
    float kk0 = k0 * kkw[c0], kk1 = k1 * kkw[c1];
    float ss = kk0*kk0 + kk1*kk1;
#pragma unroll
    for (int m = 16; m > 0; m >>= 1) ss += __shfl_xor_sync(0xffffffffu, ss, m);
    float inv = 1.f / fmaxf(sqrtf(ss), 1e-12f);
    float a0 = g_a[base + c0], a1v = g_a[base + c1];
    kk0 *= inv; kk1 *= inv;
    g_aa[base + c0] = -kk0;       g_aa[base + c1] = -kk1;
    g_bb[base + c0] = kk0 * a0;   g_bb[base + c1] = kk1 * a1v;
    g_k [base + c0] = k0 * (1.f + (a0  - 1.f) * kaw[c0]);
    g_k [base + c1] = k1 * (1.f + (a1v - 1.f) * kaw[c1]);
}

// ---------------- sequential RWKV7 scan: TMA-batched double-buffered ----------------
// 16 timesteps x 6 vectors per TMA batch; no per-step syncthreads.
#define STB  16
#define SBUF (6*STB*64)                       // floats per buffer
#define SCAN_SMEM (2*SBUF*4 + 64)

__global__ __launch_bounds__(256)
void scan_kernel(const __grid_constant__ CUtensorMap mR,
                 const __grid_constant__ CUtensorMap mW,
                 const __grid_constant__ CUtensorMap mK,
                 const __grid_constant__ CUtensorMap mAA,
                 const __grid_constant__ CUtensorMap mBB,
                 const __grid_constant__ CUtensorMap mV,
                 float* __restrict__ o)
{
    const int bh = blockIdx.x;
    const int b = bh / Hz, h = bh % Hz;
    const int tid = threadIdx.x;
    const int i  = tid >> 2;
    const int jq = tid & 3;
    const int jb = jq * 16;

    extern __shared__ __align__(128) float sm[];
    const uint32_t smb = su32(sm);
    const uint32_t ctrl = smb + 2*SBUF*4;

    if (tid == 0) { MBARRIER_INIT(ctrl, 1); MBARRIER_INIT(ctrl+8, 1); }
    __syncthreads();

    const int cx = h * 64;
    auto issue = [&](int buf, int t0) {
        uint32_t fb = ctrl + 8*buf;
        MBARRIER_EXPECT_TX(fb, (uint32_t)(SBUF*4));
        uint32_t dst = smb + buf*SBUF*4;
        int cy = b*Tz + t0;
        TMA2D(dst + 0*STB*64*4, &mR,  cx, cy, fb);
        TMA2D(dst + 1*STB*64*4, &mW,  cx, cy, fb);
        TMA2D(dst + 2*STB*64*4, &mK,  cx, cy, fb);
        TMA2D(dst + 3*STB*64*4, &mAA, cx, cy, fb);
        TMA2D(dst + 4*STB*64*4, &mBB, cx, cy, fb);
        TMA2D(dst + 5*STB*64*4, &mV,  cx, cy, fb);
    };

    if (tid == 0) { issue(0, 0); issue(1, STB); }

    u64 S2[8];
#pragma unroll
    for (int q = 0; q < 8; q++) S2[q] = 0ULL;

    float* obase = o + (size_t)b * Tz * Cz + h * 64;
    int ph[2] = {0, 0};
    const int NTB = Tz / STB;

    for (int tb = 0; tb < NTB; tb++) {
        const int buf = tb & 1;
        mbar_wait(ctrl + 8*buf, ph[buf]);
        ph[buf] ^= 1;
        const float* base_ = sm + buf*SBUF;

        for (int tt = 0; tt < STB; tt++) {
            const float* s_r  = base_ + 0*STB*64 + tt*64;
            const float* s_w  = base_ + 1*STB*64 + tt*64;
            const float* s_k  = base_ + 2*STB*64 + tt*64;
            const float* s_aa = base_ + 3*STB*64 + tt*64;
            const float* s_bb = base_ + 4*STB*64 + tt*64;
            const float* s_v  = base_ + 5*STB*64 + tt*64;

            u64 p0 = 0ULL, p1 = 0ULL;
#pragma unroll
            for (int g = 0; g < 4; g++) {
                ulonglong2 a2 = *(const ulonglong2*)&s_aa[jb + 4*g];
                p0 = ffma2(S2[2*g],   a2.x, p0);
                p1 = ffma2(S2[2*g+1], a2.y, p1);
            }
            float2 f0 = unpack2(p0), f1 = unpack2(p1);
            float sa = (f0.x + f0.y) + (f1.x + f1.y);
            sa += __shfl_xor_sync(0xffffffffu, sa, 1);
            sa += __shfl_xor_sync(0xffffffffu, sa, 2);
            const u64 sa2 = pack2(sa, sa);
            const float vi = s_v[i];
            const u64 vi2 = pack2(vi, vi);

            u64 o0 = 0ULL, o1 = 0ULL;
#pragma unroll
            for (int g = 0; g < 4; g++) {
                ulonglong2 w2 = *(const ulonglong2*)&s_w [jb + 4*g];
                ulonglong2 b2 = *(const ulonglong2*)&s_bb[jb + 4*g];
                ulonglong2 k2 = *(const ulonglong2*)&s_k [jb + 4*g];
                ulonglong2 r2 = *(const ulonglong2*)&s_r [jb + 4*g];
                S2[2*g]   = ffma2(S2[2*g],   w2.x, ffma2(sa2, b2.x, fmul2(vi2, k2.x)));
                o0        = ffma2(S2[2*g],   r2.x, o0);
                S2[2*g+1] = ffma2(S2[2*g+1], w2.y, ffma2(sa2, b2.y, fmul2(vi2, k2.y)));
                o1        = ffma2(S2[2*g+1], r2.y, o1);
            }
            float2 q0 = unpack2(o0), q1 = unpack2(o1);
            float out = (q0.x + q0.y) + (q1.x + q1.y);
            out += __shfl_xor_sync(0xffffffffu, out, 1);
            out += __shfl_xor_sync(0xffffffffu, out, 2);
            if (jq == 0) obase[(size_t)(tb*STB + tt) * Cz + i] = out;
        }

        __syncthreads();   // all threads done reading buf
        if (tid == 0 && tb + 2 < NTB) issue(buf, (tb + 2) * STB);
    }
}

// ---------------- groupnorm + rk bonus + gate -> fp16 ----------------
__global__ void post_kernel(const float* __restrict__ rk,
                            const float* __restrict__ gamma, const float* __restrict__ beta)
{
    int gw   = (blockIdx.x * blockDim.x + threadIdx.x) >> 5;
    int lane = threadIdx.x & 31;
    if (gw >= BTz * Hz) return;
    int bt = gw / Hz, h = gw % Hz;
    int c0 = h * 64 + lane, c1 = c0 + 32;
    size_t base = (size_t)bt * Cz;
    float o0 = g_o[base + c0], o1 = g_o[base + c1];
    float s1 = o0 + o1;
    float s2 = o0*o0 + o1*o1;
    float r0 = g_r[base + c0], r1 = g_r[base + c1];
    float k0 = g_k[base + c0], k1 = g_k[base + c1];
    float bon = r0 * k0 * rk[h * 64 + lane] + r1 * k1 * rk[h * 64 + lane + 32];
#pragma unroll
    for (int m = 16; m > 0; m >>= 1) {
        s1  += __shfl_xor_sync(0xffffffffu, s1,  m);
        s2  += __shfl_xor_sync(0xffffffffu, s2,  m);
        bon += __shfl_xor_sync(0xffffffffu, bon, m);
    }
    float mu   = s1 * (1.f / 64.f);
    float var  = s2 * (1.f / 64.f) - mu * mu;
    float rstd = rsqrtf(var + 0.00064f);
    float v0 = g_v[base + c0], v1 = g_v[base + c1];
    float y0 = ((o0 - mu) * rstd * gamma[c0] + beta[c0] + bon * v0) * g_g[base + c0];
    float y1 = ((o1 - mu) * rstd * gamma[c1] + beta[c1] + bon * v1) * g_g[base + c1];
    g_yg[base + c0] = __float2half_rn(y0);
    g_yg[base + c1] = __float2half_rn(y1);
}

// ---------------- host: tensormap builders ----------------
typedef CUresult (*PFN_encode)(CUtensorMap*, CUtensorMapDataType, cuuint32_t, void*,
                               const cuuint64_t*, const cuuint64_t*, const cuuint32_t*,
                               const cuuint32_t*, CUtensorMapInterleave, CUtensorMapSwizzle,
                               CUtensorMapL2promotion, CUtensorMapFloatOOBfill);

static void make_map(PFN_encode enc, CUtensorMap* m, const void* base,
                     unsigned long long d0, unsigned long long d1,
                     unsigned long long stride1B, unsigned box0, unsigned box1)
{
    cuuint64_t dims[2]    = { d0, d1 };
    cuuint64_t strides[1] = { stride1B };
    cuuint32_t box[2]     = { box0, box1 };
    cuuint32_t es[2]      = { 1, 1 };
    enc(m, CU_TENSOR_MAP_DATA_TYPE_FLOAT16, 2, (void*)base, dims, strides, box, es,
        CU_TENSOR_MAP_INTERLEAVE_NONE, CU_TENSOR_MAP_SWIZZLE_128B,
        CU_TENSOR_MAP_L2_PROMOTION_L2_128B, CU_TENSOR_MAP_FLOAT_OOB_FILL_NONE);
}

static void make_map_f32(PFN_encode enc, CUtensorMap* m, const void* base,
                         unsigned long long d0, unsigned long long d1,
                         unsigned long long stride1B, unsigned box0, unsigned box1)
{
    cuuint64_t dims[2]    = { d0, d1 };
    cuuint64_t strides[1] = { stride1B };
    cuuint32_t box[2]     = { box0, box1 };
    cuuint32_t es[2]      = { 1, 1 };
    enc(m, CU_TENSOR_MAP_DATA_TYPE_FLOAT32, 2, (void*)base, dims, strides, box, es,
        CU_TENSOR_MAP_INTERLEAVE_NONE, CU_TENSOR_MAP_SWIZZLE_NONE,
        CU_TENSOR_MAP_L2_PROMOTION_L2_128B, CU_TENSOR_MAP_FLOAT_OOB_FILL_NONE);
}

#define SMEM_128 (2048 + 2*(128*128 + 2*128*128))
#define SMEM_64  (2048 + 2*(128*128 + 2*64*128))

// ---------------- launch ----------------
extern "C" void kernel_launch(void* const* d_in, const int* in_sizes, int n_in,
                              void* d_out, int out_size)
{
    const float* x    = (const float*)d_in[0];
    const float* x_r  = (const float*)d_in[1];
    const float* x_w  = (const float*)d_in[2];
    const float* x_k  = (const float*)d_in[3];
    const float* x_v  = (const float*)d_in[4];
    const float* x_a  = (const float*)d_in[5];
    const float* x_g  = (const float*)d_in[6];
    const float* w0   = (const float*)d_in[7];
    const float* w1   = (const float*)d_in[8];
    const float* w2   = (const float*)d_in[9];
    const float* a0   = (const float*)d_in[10];
    const float* a1   = (const float*)d_in[11];
    const float* a2   = (const float*)d_in[12];
    const float* g1   = (const float*)d_in[16];
    const float* g2   = (const float*)d_in[17];
    const float* k_k  = (const float*)d_in[18];
    const float* k_a  = (const float*)d_in[19];
    const float* r_k  = (const float*)d_in[20];
    const float* Wr   = (const float*)d_in[21];
    const float* Wk   = (const float*)d_in[22];
    const float* Wv   = (const float*)d_in[23];
    const float* Wo   = (const float*)d_in[24];
    const float* lg   = (const float*)d_in[25];
    const float* lb   = (const float*)d_in[26];

    void *pr, *pk, *pv, *pwd, *pa, *pg, *paa, *pbb, *po;
    void *px6, *pyg, *phid, *pwh, *pwl;
    cudaGetSymbolAddress(&pr,  g_r);   cudaGetSymbolAddress(&pk,  g_k);
    cudaGetSymbolAddress(&pv,  g_v);   cudaGetSymbolAddress(&pwd, g_wd);
    cudaGetSymbolAddress(&pa,  g_a);   cudaGetSymbolAddress(&pg,  g_g);
    cudaGetSymbolAddress(&paa, g_aa);  cudaGetSymbolAddress(&pbb, g_bb);
    cudaGetSymbolAddress(&po,  g_o);
    cudaGetSymbolAddress(&px6, g_x6);  cudaGetSymbolAddress(&pyg, g_yg);
    cudaGetSymbolAddress(&phid, g_hid);
    cudaGetSymbolAddress(&pwh, g_wh);  cudaGetSymbolAddress(&pwl, g_wl);

    float *rb = (float*)pr, *kb = (float*)pk, *vb = (float*)pv, *wd = (float*)pwd;
    float *ab = (float*)pa, *gb = (float*)pg, *aab = (float*)paa, *bbb = (float*)pbb;
    float *ob = (float*)po;
    f16 *x6 = (f16*)px6, *yg = (f16*)pyg, *hid = (f16*)phid;
    f16 *wh = (f16*)pwh, *wl = (f16*)pwl;

    const size_t S = (size_t)BTz * Cz;

    cudaFuncSetAttribute(tc_gemm6<128>, cudaFuncAttributeMaxDynamicSharedMemorySize, SMEM_128);
    cudaFuncSetAttribute(tc_gemm3h<64>, cudaFuncAttributeMaxDynamicSharedMemorySize, SMEM_64);
    cudaFuncSetAttribute(scan_kernel,   cudaFuncAttributeMaxDynamicSharedMemorySize, SCAN_SMEM);

    PFN_encode enc = nullptr;
    cudaDriverEntryPointQueryResult qres;
    cudaGetDriverEntryPoint("cuTensorMapEncodeTiled", (void**)&enc,
                            cudaEnableDefault, &qres);

    // 1. transpose+split all weights into the pool
    TJobs jb;
    jb.src[0]=Wr; jb.src[1]=Wk; jb.src[2]=Wv; jb.src[3]=Wo;
    jb.src[4]=w1; jb.src[5]=a1; jb.src[6]=g1;
    jb.src[7]=w2; jb.src[8]=a2; jb.src[9]=g2;
    jb.dstoff[0]=O_Wr; jb.dstoff[1]=O_Wk; jb.dstoff[2]=O_Wv; jb.dstoff[3]=O_Wo;
    jb.dstoff[4]=O_L1; jb.dstoff[5]=O_L1+64*Cz; jb.dstoff[6]=O_L1+128*Cz;
    jb.dstoff[7]=O_W2T; jb.dstoff[8]=O_A2T; jb.dstoff[9]=O_G2T;
    jb.K[0]=jb.K[1]=jb.K[2]=jb.K[3]=Cz; jb.K[4]=jb.K[5]=jb.K[6]=Cz;
    jb.K[7]=64; jb.K[8]=64; jb.K[9]=128;
    jb.N[0]=jb.N[1]=jb.N[2]=jb.N[3]=Cz; jb.N[4]=64; jb.N[5]=64; jb.N[6]=128;
    jb.N[7]=Cz; jb.N[8]=Cz; jb.N[9]=Cz;
    int tb = 0;
    for (int j = 0; j < 10; j++) { jb.tbase[j] = tb; tb += (jb.K[j]/32)*(jb.N[j]/32); }
    jb.tbase[10] = tb;
    tsplit_kernel<<<tb, dim3(32,8)>>>(jb, wh, wl);

    // 2. token shift + mix
    mix_kernel<<<(BTz*Cz/4 + 255)/256, 256>>>(x, x_r, x_w, x_k, x_v, x_a, x_g, x6);

    CUtensorMap A0, A1, A2, B0h, B1h, B2h, B0l, B1l, B2l;

    // 3. fused LoRA stage-1: z0 hw=tanh(xw@w1), z1 ha=xa@a1, z2 hg=sig(xg@g1)
    make_map(enc, &A0,  x6 + 1*S, Cz, BTz, Cz*2, 64, 128);
    make_map(enc, &A1,  x6 + 4*S, Cz, BTz, Cz*2, 64, 128);
    make_map(enc, &A2,  x6 + 5*S, Cz, BTz, Cz*2, 64, 128);
    make_map(enc, &B0h, wh + O_L1,          Cz, 64,  Cz*2, 64, 64);
    make_map(enc, &B1h, wh + O_L1 + 64*Cz,  Cz, 64,  Cz*2, 64, 64);
    make_map(enc, &B2h, wh + O_L1 + 128*Cz, Cz, 128, Cz*2, 64, 64);
    make_map(enc, &B0l, wl + O_L1,          Cz, 64,  Cz*2, 64, 64);
    make_map(enc, &B1l, wl + O_L1 + 64*Cz,  Cz, 64,  Cz*2, 64, 64);
    make_map(enc, &B2l, wl + O_L1 + 128*Cz, Cz, 128, Cz*2, 64, 64);
    tc_gemm3h<64><<<dim3(2, BTz/128, 3), 256, SMEM_64>>>(
        A0, A1, A2, B0h, B1h, B2h, B0l, B1l, B2l,
        hid, hid + 64, hid + 128,
        256, 1, 0, 2, 1, 1, 2);

    // 4. ONE launch: r, k, v projections + LoRA stage-2 (6 jobs)
    G6 g6;
    make_map(enc, &g6.A[0], x6 + 0*S, Cz, BTz, Cz*2, 64, 128);
    make_map(enc, &g6.A[1], x6 + 2*S, Cz, BTz, Cz*2, 64, 128);
    make_map(enc, &g6.A[2], x6 + 3*S, Cz, BTz, Cz*2, 64, 128);
    make_map(enc, &g6.A[3], hid,       64,  BTz, 256*2, 64, 128);
    make_map(enc, &g6.A[4], hid + 64,  64,  BTz, 256*2, 64, 128);
    make_map(enc, &g6.A[5], hid + 128, 128, BTz, 256*2, 64, 128);
    make_map(enc, &g6.Bh[0], wh + O_Wr,  Cz,  Cz, Cz*2,  64, 128);
    make_map(enc, &g6.Bh[1], wh + O_Wk,  Cz,  Cz, Cz*2,  64, 128);
    make_map(enc, &g6.Bh[2], wh + O_Wv,  Cz,  Cz, Cz*2,  64, 128);
    make_map(enc, &g6.Bh[3], wh + O_W2T, 64,  Cz, 64*2,  64, 128);
    make_map(enc, &g6.Bh[4], wh + O_A2T, 64,  Cz, 64*2,  64, 128);
    make_map(enc, &g6.Bh[5], wh + O_G2T, 128, Cz, 128*2, 64, 128);
    make_map(enc, &g6.Bl[0], wl + O_Wr,  Cz,  Cz, Cz*2,  64, 128);
    make_map(enc, &g6.Bl[1], wl + O_Wk,  Cz,  Cz, Cz*2,  64, 128);
    make_map(enc, &g6.Bl[2], wl + O_Wv,  Cz,  Cz, Cz*2,  64, 128);
    make_map(enc, &g6.Bl[3], wl + O_W2T, 64,  Cz, 64*2,  64, 128);
    make_map(enc, &g6.Bl[4], wl + O_A2T, 64,  Cz, 64*2,  64, 128);
    make_map(enc, &g6.Bl[5], wl + O_G2T, 128, Cz, 128*2, 64, 128);
    g6.K[0] = Cz; g6.K[1] = Cz; g6.K[2] = Cz; g6.K[3] = 64; g6.K[4] = 64; g6.K[5] = 128;
    g6.C[0] = rb; g6.C[1] = kb; g6.C[2] = vb; g6.C[3] = wd; g6.C[4] = ab; g6.C[5] = gb;
    g6.bias[0] = nullptr; g6.bias[1] = nullptr; g6.bias[2] = nullptr;
    g6.bias[3] = w0; g6.bias[4] = a0; g6.bias[5] = nullptr;
    g6.epi[0] = 0; g6.epi[1] = 0; g6.epi[2] = 0; g6.epi[3] = 3; g6.epi[4] = 2; g6.epi[5] = 0;
    tc_gemm6<128><<<dim3(8, BTz/128, 6), 256, SMEM_128>>>(g6, Cz);

    // 5. kk normalize / aa / bb / k update (parallel)
    prep_kernel<<<BTz*Hz/8, 256>>>(k_k, k_a);

    // 6. sequential scan (TMA-batched)
    {
        CUtensorMap sR, sW, sK, sAA, sBB, sV;
        make_map_f32(enc, &sR,  rb,  Cz, BTz, Cz*4, 64, STB);
        make_map_f32(enc, &sW,  wd,  Cz, BTz, Cz*4, 64, STB);
        make_map_f32(enc, &sK,  kb,  Cz, BTz, Cz*4, 64, STB);
        make_map_f32(enc, &sAA, aab, Cz, BTz, Cz*4, 64, STB);
        make_map_f32(enc, &sBB, bbb, Cz, BTz, Cz*4, 64, STB);
        make_map_f32(enc, &sV,  vb,  Cz, BTz, Cz*4, 64, STB);
        scan_kernel<<<Bz*Hz, 256, SCAN_SMEM>>>(sR, sW, sK, sAA, sBB, sV, ob);
    }

    // 7. groupnorm + bonus + gate -> yg fp16
    post_kernel<<<BTz*Hz/8, 256>>>(r_k, lg, lb);

    // 8. output projection (1 job)
    G6 go;
    make_map(enc, &go.A[0],  yg, Cz, BTz, Cz*2, 64, 128);
    make_map(enc, &go.Bh[0], wh + O_Wo, Cz, Cz, Cz*2, 64, 128);
    make_map(enc, &go.Bl[0], wl + O_Wo, Cz, Cz, Cz*2, 64, 128);
    for (int z = 1; z < 6; z++) { go.A[z] = go.A[0]; go.Bh[z] = go.Bh[0]; go.Bl[z] = go.Bl[0]; }
    for (int z = 0; z < 6; z++) { go.K[z] = Cz; go.C[z] = (float*)d_out; go.bias[z] = nullptr; go.epi[z] = 0; }
    tc_gemm6<128><<<dim3(8, BTz/128, 1), 256, SMEM_128>>>(go, Cz);

    // 9. v_first if expected
    if (out_size >= 2 * BTz * Cz) {
        cudaMemcpyAsync((float*)d_out + S, vb, sizeof(float) * S, cudaMemcpyDeviceToDevice);
    }
}

// round 16
// speedup vs baseline: 1.8072x; 1.4903x over previous
#include <cuda_runtime.h>
#include <cuda.h>
#include <cuda_bf16.h>
#include <cuda_fp16.h>
#include <cstdint>
#include <math.h>

#define Bz   4
#define Tz   1024
#define Cz   1024
#define Hz   16
#define BTz  (Bz*Tz)

typedef __half  f16;
typedef __half2 f162;
typedef unsigned long long u64;

// ---------------- scratch (device globals; no allocation allowed) ----------------
__device__ float g_r [BTz*Cz], g_k [BTz*Cz], g_v [BTz*Cz], g_wd[BTz*Cz];
__device__ float g_a [BTz*Cz], g_g [BTz*Cz], g_aa[BTz*Cz], g_bb[BTz*Cz], g_o [BTz*Cz];

__device__ __align__(256) f16 g_x6[6*BTz*Cz];     // mixed streams, fp16
__device__ __align__(256) f16 g_yg[BTz*Cz];       // (gn(o)+bonus)*g fp16
// LoRA hidden pool [BTz, 256]: cols 0-63 decay, 64-127 a, 128-255 g (fp16)
__device__ __align__(256) f16 g_hid[BTz*256];

// weight pool: all matrices stored TRANSPOSED [N, K] row-major, fp16 hi/lo
#define O_Wr 0
#define O_Wk (Cz*Cz)
#define O_Wv (2*Cz*Cz)
#define O_Wo (3*Cz*Cz)
#define O_L1 (4*Cz*Cz)                  // [256, 1024]: w1t 0-63, a1t 64-127, g1t 128-255
#define O_W2T (O_L1 + 256*Cz)           // [1024, 64]
#define O_A2T (O_W2T + Cz*64)           // [1024, 64]
#define O_G2T (O_A2T + Cz*64)           // [1024, 128]
#define WPOOL (O_G2T + Cz*128)
__device__ __align__(256) f16 g_wh[WPOOL], g_wl[WPOOL];

// ---------------- helpers ----------------
__device__ __forceinline__ uint32_t su32(const void* p) {
    return (uint32_t)__cvta_generic_to_shared(p);
}
__device__ __forceinline__ void ldsm4(uint32_t& a0, uint32_t& a1, uint32_t& a2, uint32_t& a3, uint32_t addr) {
    asm volatile("ldmatrix.sync.aligned.m8n8.x4.shared.b16 {%0,%1,%2,%3},[%4];"
                 : "=r"(a0), "=r"(a1), "=r"(a2), "=r"(a3) : "r"(addr));
}
__device__ __forceinline__ void mma16816(float* c, const uint32_t* a, const uint32_t* b) {
    asm volatile("mma.sync.aligned.m16n8k16.row.col.f32.f16.f16.f32 "
                 "{%0,%1,%2,%3},{%4,%5,%6,%7},{%8,%9},{%0,%1,%2,%3};"
                 : "+f"(c[0]), "+f"(c[1]), "+f"(c[2]), "+f"(c[3])
                 : "r"(a[0]), "r"(a[1]), "r"(a[2]), "r"(a[3]), "r"(b[0]), "r"(b[1]));
}
__device__ __forceinline__ u64 ffma2(u64 a, u64 b, u64 c) {
    u64 d; asm("fma.rn.f32x2 %0,%1,%2,%3;" : "=l"(d) : "l"(a), "l"(b), "l"(c)); return d;
}
__device__ __forceinline__ u64 fmul2(u64 a, u64 b) {
    u64 d; asm("mul.rn.f32x2 %0,%1,%2;" : "=l"(d) : "l"(a), "l"(b)); return d;
}
__device__ __forceinline__ u64 pack2(float x, float y) {
    u64 d; asm("mov.b64 %0,{%1,%2};" : "=l"(d) : "f"(x), "f"(y)); return d;
}
__device__ __forceinline__ float2 unpack2(u64 a) {
    float x, y; asm("mov.b64 {%0,%1},%2;" : "=f"(x), "=f"(y) : "l"(a)); return make_float2(x, y);
}

// ---- mbarrier / TMA ----
#define MBARRIER_INIT(addr, cnt) \
    asm volatile("mbarrier.init.shared.b64 [%0], %1;" :: "r"((uint32_t)(addr)), "r"((uint32_t)(cnt)) : "memory")
#define MBARRIER_EXPECT_TX(addr, bytes) \
    asm volatile("mbarrier.arrive.expect_tx.shared.b64 _, [%0], %1;" :: "r"((uint32_t)(addr)), "r"((uint32_t)(bytes)) : "memory")
#define TMA2D(dst, map, cx, cy, mbar) \
    asm volatile("cp.async.bulk.tensor.2d.shared::cta.global.tile.mbarrier::complete_tx::bytes [%0],[%1,{%2,%3}],[%4];" \
        :: "r"((uint32_t)(dst)), "l"(map), "r"((int)(cx)), "r"((int)(cy)), "r"((uint32_t)(mbar)) : "memory")

__device__ __forceinline__ void mbar_wait(uint32_t addr, int phase) {
    asm volatile(
        "{\n\t.reg .pred P1;\n\t"
        "WAIT_LOOP_%=:\n\t"
        "mbarrier.try_wait.parity.shared.b64 P1, [%0], %1, 0x989680;\n\t"
        "@P1 bra.uni WAIT_DONE_%=;\n\t"
        "bra.uni WAIT_LOOP_%=;\n\t"
        "WAIT_DONE_%=:\n\t}"
        :: "r"(addr), "r"((uint32_t)phase) : "memory");
}

// ---------------- transpose + split: W[K,N] fp32 -> pool[N,K] fp16 hi/lo ----------------
struct TJobs { const float* src[10]; int dstoff[10]; int K[10]; int N[10]; int tbase[11]; };

__global__ void tsplit_kernel(TJobs jb, f16* __restrict__ hi, f16* __restrict__ lo)
{
    __shared__ float s[32][33];
    int bid = blockIdx.x;
    int j = 0;
#pragma unroll
    for (int q = 1; q < 10; q++) if (bid >= jb.tbase[q]) j = q;
    int tl = bid - jb.tbase[j];
    int K = jb.K[j], N = jb.N[j];
    int ntn = N >> 5;
    int tn = tl % ntn, tk = tl / ntn;
    const float* src = jb.src[j];
    int tx = threadIdx.x, ty = threadIdx.y;   // 32 x 8
#pragma unroll
    for (int i = 0; i < 4; i++) {
        int r = tk*32 + ty + i*8, c = tn*32 + tx;
        s[ty + i*8][tx] = src[(size_t)r * N + c];
    }
    __syncthreads();
#pragma unroll
    for (int i = 0; i < 4; i++) {
        int n = tn*32 + ty + i*8, k = tk*32 + tx;
        float v = s[tx][ty + i*8];
        f16 h = __float2half_rn(v);
        size_t di = (size_t)jb.dstoff[j] + (size_t)n * K + k;
        hi[di] = h;
        lo[di] = __float2half_rn(v - __half2float(h));
    }
}

// ---------------- token shift + 6-way mix, emitting fp16 ----------------
__global__ void mix_kernel(const float* __restrict__ x,
                           const float* __restrict__ mr, const float* __restrict__ mw,
                           const float* __restrict__ mk, const float* __restrict__ mv,
                           const float* __restrict__ ma, const float* __restrict__ mg,
                           f16* __restrict__ xo)
{
    int idx = blockIdx.x * blockDim.x + threadIdx.x;     // float4 index
    const int total = BTz * Cz / 4;
    if (idx >= total) return;
    int c4 = idx % (Cz / 4);
    int bt = idx / (Cz / 4);
    int t  = bt % Tz;
    const float4* x4 = (const float4*)x;
    float4 cur = x4[idx];
    float4 prev = make_float4(0.f, 0.f, 0.f, 0.f);
    if (t > 0) prev = x4[idx - Cz / 4];
    float4 xx = make_float4(prev.x - cur.x, prev.y - cur.y, prev.z - cur.z, prev.w - cur.w);
    int c = c4 * 4;
    const float* ms[6] = { mr, mw, mk, mv, ma, mg };
#pragma unroll
    for (int s = 0; s < 6; s++) {
        float4 mm = *(const float4*)(ms[s] + c);
        f162 h0 = __floats2half2_rn(cur.x + xx.x * mm.x, cur.y + xx.y * mm.y);
        f162 h1 = __floats2half2_rn(cur.z + xx.z * mm.z, cur.w + xx.w * mm.w);
        uint2 h; h.x = *(uint32_t*)&h0; h.y = *(uint32_t*)&h1;
        ((uint2*)(xo + (size_t)s * BTz * Cz))[idx] = h;
    }
}

// ---------------- epilogue ----------------
__device__ __forceinline__ float apply_epi_rt(float acc, float b, int epi)
{
    float pre = acc + b;
    if (epi == 0) return pre;
    if (epi == 1) return tanhf(pre);
    if (epi == 2) return 1.f / (1.f + expf(-pre));
    float sp = (pre > -30.f) ? log1pf(expf(-pre)) : -pre;   // softplus(-pre)
    return expf(-expf(-sp - 0.5f));
}

// ---------------- 6-job TMA + mma.sync GEMM: C = A*Bh + A*Bl ----------------
struct G6 {
    CUtensorMap A[6], Bh[6], Bl[6];
    int K[6];
    float* C[6];
    const float* bias[6];
    int epi[6];
};

template<int BN>
__global__ __launch_bounds__(256, 2)
void tc_gemm6(const __grid_constant__ G6 jobs, int ldc)
{
    constexpr int BM = 128;
    constexpr int ATILE = BM*128;
    constexpr int BTILE = BN*128;
    constexpr int STAGE = ATILE + 2*BTILE;
    constexpr int NSTG = 2;
    constexpr int WM = 64;
    constexpr int WN = 32;
    constexpr int MFR = WM/16, NFR = WN/8;

    const int z = blockIdx.z;
    const CUtensorMap* pA  = &jobs.A[z];
    const CUtensorMap* pBh = &jobs.Bh[z];
    const CUtensorMap* pBl = &jobs.Bl[z];
    const int K   = jobs.K[z];
    float* C      = jobs.C[z];
    const float* bias = jobs.bias[z];
    const int epi = jobs.epi[z];

    extern __shared__ __align__(1024) char dsm[];
    uint32_t raw  = su32(dsm);
    uint32_t ctrl = (raw + 1023u) & ~1023u;
    uint32_t tiles = ctrl + 1024;

    const int tid = threadIdx.x, lane = tid & 31, warp = tid >> 5;
    const int wN = warp % (BN/WN), wM = warp / (BN/WN);
    const int row0 = blockIdx.y * BM, col0 = blockIdx.x * BN;
    const int T = K >> 6;

    if (tid == 0) {
#pragma unroll
        for (int s = 0; s < NSTG; s++) MBARRIER_INIT(ctrl + 16 + 8*s, 1);
    }
    __syncthreads();

    float acc[MFR][NFR][4];
#pragma unroll
    for (int i = 0; i < MFR; i++)
#pragma unroll
        for (int j = 0; j < NFR; j++)
#pragma unroll
            for (int q = 0; q < 4; q++) acc[i][j][q] = 0.f;

    const uint32_t swm = (uint32_t)((lane & 7) << 4);
    uint32_t aRow[MFR], bRow[NFR/2];
#pragma unroll
    for (int fm = 0; fm < MFR; fm++)
        aRow[fm] = (uint32_t)((wM*WM + fm*16 + (lane & 15)) * 128);
#pragma unroll
    for (int p = 0; p < NFR/2; p++)
        bRow[p] = (uint32_t)((wN*WN + p*16 + (lane & 7) + ((lane >> 4) << 3)) * 128);
    const uint32_t aColB = (uint32_t)((lane >> 4) * 16);
    const uint32_t bColB = (uint32_t)(((lane >> 3) & 1) * 16);

    auto issue_stage = [&](int s, int k0) {
        uint32_t sb = tiles + s*STAGE;
        uint32_t fb = ctrl + 16 + 8*s;
        MBARRIER_EXPECT_TX(fb, (uint32_t)STAGE);
        TMA2D(sb,             pA,  k0, row0, fb);
        TMA2D(sb+ATILE,       pBh, k0, col0, fb);
        TMA2D(sb+ATILE+BTILE, pBl, k0, col0, fb);
    };

    if (tid == 0) {
        const int npre = (T < NSTG) ? T : NSTG;
        for (int s = 0; s < npre; s++) issue_stage(s, s*64);
    }

    int ph[NSTG];
#pragma unroll
    for (int s = 0; s < NSTG; s++) ph[s] = 0;

    for (int t = 0; t < T; t++) {
        const int s = t & (NSTG-1);
        mbar_wait(ctrl + 16 + 8*s, ph[s]);
        ph[s] ^= 1;
        const uint32_t aB = tiles + s*STAGE;
        const uint32_t bH = aB + ATILE;
        const uint32_t bL = bH + BTILE;
#pragma unroll
        for (int kk = 0; kk < 4; kk++) {
            const uint32_t aC = (uint32_t)(kk*32) + aColB;
            const uint32_t bC = (uint32_t)(kk*32) + bColB;
            uint32_t Af[MFR][4], Bfh[NFR][2], Bfl[NFR][2];
#pragma unroll
            for (int fm = 0; fm < MFR; fm++) {
                uint32_t off = aRow[fm] + (aC ^ swm);
                ldsm4(Af[fm][0], Af[fm][1], Af[fm][2], Af[fm][3], aB + off);
            }
#pragma unroll
            for (int p = 0; p < NFR/2; p++) {
                uint32_t off = bRow[p] + (bC ^ swm);
                uint32_t t0, t1, t2, t3;
                ldsm4(t0, t1, t2, t3, bH + off);
                Bfh[2*p][0] = t0; Bfh[2*p][1] = t1; Bfh[2*p+1][0] = t2; Bfh[2*p+1][1] = t3;
                ldsm4(t0, t1, t2, t3, bL + off);
                Bfl[2*p][0] = t0; Bfl[2*p][1] = t1; Bfl[2*p+1][0] = t2; Bfl[2*p+1][1] = t3;
            }
#pragma unroll
            for (int fm = 0; fm < MFR; fm++)
#pragma unroll
                for (int fn = 0; fn < NFR; fn++) {
                    mma16816(acc[fm][fn], Af[fm], Bfh[fn]);
                    mma16816(acc[fm][fn], Af[fm], Bfl[fn]);
                }
        }
        __syncthreads();
        if (tid == 0 && t + NSTG < T) issue_stage(s, (t + NSTG) * 64);
    }

    // epilogue
#pragma unroll
    for (int fm = 0; fm < MFR; fm++) {
        int r = row0 + wM*WM + fm*16 + (lane >> 2);
#pragma unroll
        for (int fn = 0; fn < NFR; fn++) {
            int c = col0 + wN*WN + fn*8 + 2*(lane & 3);
            float b0 = bias ? bias[c] : 0.f;
            float b1 = bias ? bias[c+1] : 0.f;
            float x0 = apply_epi_rt(acc[fm][fn][0], b0, epi);
            float x1 = apply_epi_rt(acc[fm][fn][1], b1, epi);
            float x2 = apply_epi_rt(acc[fm][fn][2], b0, epi);
            float x3 = apply_epi_rt(acc[fm][fn][3], b1, epi);
            *(float2*)&C[(size_t)r*ldc + c]     = make_float2(x0, x1);
            *(float2*)&C[(size_t)(r+8)*ldc + c] = make_float2(x2, x3);
        }
    }
}

// ---------------- 3-job LoRA stage-1 GEMM (BN=64, fp16 out) ----------------
template<int BN>
__global__ __launch_bounds__(256, 2)
void tc_gemm3h(const __grid_constant__ CUtensorMap mA0,
               const __grid_constant__ CUtensorMap mA1,
               const __grid_constant__ CUtensorMap mA2,
               const __grid_constant__ CUtensorMap mB0h,
               const __grid_constant__ CUtensorMap mB1h,
               const __grid_constant__ CUtensorMap mB2h,
               const __grid_constant__ CUtensorMap mB0l,
               const __grid_constant__ CUtensorMap mB1l,
               const __grid_constant__ CUtensorMap mB2l,
               f16* H0, f16* H1, f16* H2,
               int ldc, int epi0, int epi1, int epi2,
               int xc0, int xc1, int xc2)
{
    constexpr int BM = 128;
    constexpr int ATILE = BM*128;
    constexpr int BTILE = BN*128;
    constexpr int STAGE = ATILE + 2*BTILE;
    constexpr int NSTG = 2;
    constexpr int WM = 32, WN = 32;
    constexpr int MFR = WM/16, NFR = WN/8;

    const int z = blockIdx.z;
    const int xcnt = (z == 0) ? xc0 : (z == 1) ? xc1 : xc2;
    if ((int)blockIdx.x >= xcnt) return;

    const CUtensorMap* pA  = (z == 0) ? &mA0  : (z == 1) ? &mA1  : &mA2;
    const CUtensorMap* pBh = (z == 0) ? &mB0h : (z == 1) ? &mB1h : &mB2h;
    const CUtensorMap* pBl = (z == 0) ? &mB0l : (z == 1) ? &mB1l : &mB2l;
    f16* Ch = (z == 0) ? H0 : (z == 1) ? H1 : H2;
    const int epi = (z == 0) ? epi0 : (z == 1) ? epi1 : epi2;
    const int K = Cz;

    extern __shared__ __align__(1024) char dsm[];
    uint32_t raw  = su32(dsm);
    uint32_t ctrl = (raw + 1023u) & ~1023u;
    uint32_t tiles = ctrl + 1024;

    const int tid = threadIdx.x, lane = tid & 31, warp = tid >> 5;
    const int wN = warp % (BN/WN), wM = warp / (BN/WN);
    const int row0 = blockIdx.y * BM, col0 = blockIdx.x * BN;
    const int T = K >> 6;

    if (tid == 0) {
#pragma unroll
        for (int s = 0; s < NSTG; s++) MBARRIER_INIT(ctrl + 16 + 8*s, 1);
    }
    __syncthreads();

    float acc[MFR][NFR][4];
#pragma unroll
    for (int i = 0; i < MFR; i++)
#pragma unroll
        for (int j = 0; j < NFR; j++)
#pragma unroll
            for (int q = 0; q < 4; q++) acc[i][j][q] = 0.f;

    const uint32_t swm = (uint32_t)((lane & 7) << 4);
    uint32_t aRow[MFR], bRow[NFR/2];
#pragma unroll
    for (int fm = 0; fm < MFR; fm++)
        aRow[fm] = (uint32_t)((wM*WM + fm*16 + (lane & 15)) * 128);
#pragma unroll
    for (int p = 0; p < NFR/2; p++)
        bRow[p] = (uint32_t)((wN*WN + p*16 + (lane & 7) + ((lane >> 4) << 3)) * 128);
    const uint32_t aColB = (uint32_t)((lane >> 4) * 16);
    const uint32_t bColB = (uint32_t)(((lane >> 3) & 1) * 16);

    auto issue_stage = [&](int s, int k0) {
        uint32_t sb = tiles + s*STAGE;
        uint32_t fb = ctrl + 16 + 8*s;
        MBARRIER_EXPECT_TX(fb, (uint32_t)STAGE);
        TMA2D(sb,             pA,  k0, row0, fb);
        TMA2D(sb+ATILE,       pBh, k0, col0, fb);
        TMA2D(sb+ATILE+BTILE, pBl, k0, col0, fb);
    };

    if (tid == 0) { issue_stage(0, 0); if (T > 1) issue_stage(1, 64); }

    int ph[NSTG] = {0, 0};

    for (int t = 0; t < T; t++) {
        const int s = t & (NSTG-1);
        mbar_wait(ctrl + 16 + 8*s, ph[s]);
        ph[s] ^= 1;
        const uint32_t aB = tiles + s*STAGE;
        const uint32_t bH = aB + ATILE;
        const uint32_t bL = bH + BTILE;
#pragma unroll
        for (int kk = 0; kk < 4; kk++) {
            const uint32_t aC = (uint32_t)(kk*32) + aColB;
            const uint32_t bC = (uint32_t)(kk*32) + bColB;
            uint32_t Af[MFR][4], Bfh[NFR][2], Bfl[NFR][2];
#pragma unroll
            for (int fm = 0; fm < MFR; fm++) {
                uint32_t off = aRow[fm] + (aC ^ swm);
                ldsm4(Af[fm][0], Af[fm][1], Af[fm][2], Af[fm][3], aB + off);
            }
#pragma unroll
            for (int p = 0; p < NFR/2; p++) {
                uint32_t off = bRow[p] + (bC ^ swm);
                uint32_t t0, t1, t2, t3;
                ldsm4(t0, t1, t2, t3, bH + off);
                Bfh[2*p][0] = t0; Bfh[2*p][1] = t1; Bfh[2*p+1][0] = t2; Bfh[2*p+1][1] = t3;
                ldsm4(t0, t1, t2, t3, bL + off);
                Bfl[2*p][0] = t0; Bfl[2*p][1] = t1; Bfl[2*p+1][0] = t2; Bfl[2*p+1][1] = t3;
            }
#pragma unroll
            for (int fm = 0; fm < MFR; fm++)
#pragma unroll
                for (int fn = 0; fn < NFR; fn++) {
                    mma16816(acc[fm][fn], Af[fm], Bfh[fn]);
                    mma16816(acc[fm][fn], Af[fm], Bfl[fn]);
                }
        }
        __syncthreads();
        if (tid == 0 && t + NSTG < T) issue_stage(s, (t + NSTG) * 64);
    }

#pragma unroll
    for (int fm = 0; fm < MFR; fm++) {
        int r = row0 + wM*WM + fm*16 + (lane >> 2);
#pragma unroll
        for (int fn = 0; fn < NFR; fn++) {
            int c = col0 + wN*WN + fn*8 + 2*(lane & 3);
            float x0 = apply_epi_rt(acc[fm][fn][0], 0.f, epi);
            float x1 = apply_epi_rt(acc[fm][fn][1], 0.f, epi);
            float x2 = apply_epi_rt(acc[fm][fn][2], 0.f, epi);
            float x3 = apply_epi_rt(acc[fm][fn][3], 0.f, epi);
            f162 h0 = __floats2half2_rn(x0, x1);
            f162 h1 = __floats2half2_rn(x2, x3);
            *(f162*)&Ch[(size_t)r*ldc + c]     = h0;
            *(f162*)&Ch[(size_t)(r+8)*ldc + c] = h1;
        }
    }
}

// ---------------- kk normalize, aa, bb, k update (parallel) ----------------
__global__ void prep_kernel(const float* __restrict__ kkw, const float* __restrict__ kaw)
{
    int gw   = (blockIdx.x * blockDim.x + threadIdx.x) >> 5;
    int lane = threadIdx.x & 31;
    if (gw >= BTz * Hz) return;
    int bt = gw / Hz, h = gw % Hz;
    int c0 = h * 64 + lane, c1 = c0 + 32;
    size_t base = (size_t)bt * Cz;
    float k0 = g_k[base + c0], k1 = g_k[base + c1];
    float kk0 = k0 * kkw[c0], kk1 = k1 * kkw[c1];
    float ss = kk0*kk0 + kk1*kk1;
#pragma unroll
    for (int m = 16; m > 0; m >>= 1) ss += __shfl_xor_sync(0xffffffffu, ss, m);
    float inv = 1.f / fmaxf(sqrtf(ss), 1e-12f);
    float a0 = g_a[base + c0], a1v = g_a[base + c1];
    kk0 *= inv; kk1 *= inv;
    g_aa[base + c0] = -kk0;       g_aa[base + c1] = -kk1;
    g_bb[base + c0] = kk0 * a0;   g_bb[base + c1] = kk1 * a1v;
    g_k [base + c0] = k0 * (1.f + (a0  - 1.f) * kaw[c0]);
    g_k [base + c1] = k1 * (1.f + (a1v - 1.f) * kaw[c1]);
}

// ---------------- sequential RWKV7 scan: TMA-batched, row-split ----------------
// State rows are independent: split each (b,h) into RSPLIT row-groups (blockIdx.y).
// 256 threads: row = tid>>3 (32 rows/block), jq = tid&7 (8 cols each).
#define STB  16
#define SBUF (6*STB*64)                       // floats per buffer
#define SCAN_SMEM (2*SBUF*4 + 64)
#define RSPLIT 2
#define RPB (64/RSPLIT)                       // 32 rows per block

__global__ __launch_bounds__(256)
void scan_kernel(const __grid_constant__ CUtensorMap mR,
                 const __grid_constant__ CUtensorMap mW,
                 const __grid_constant__ CUtensorMap mK,
                 const __grid_constant__ CUtensorMap mAA,
                 const __grid_constant__ CUtensorMap mBB,
                 const __grid_constant__ CUtensorMap mV,
                 float* __restrict__ o)
{
    const int bh = blockIdx.x;
    const int rg = blockIdx.y;
    const int b = bh / Hz, h = bh % Hz;
    const int tid = threadIdx.x;
    const int row = tid >> 3;                 // 0..31 local row
    const int i   = rg * RPB + row;           // global value-row 0..63
    const int jq  = tid & 7;
    const int jb  = jq * 8;                   // 8 cols per thread

    extern __shared__ __align__(128) float sm[];
    const uint32_t smb = su32(sm);
    const uint32_t ctrl = smb + 2*SBUF*4;

    if (tid == 0) { MBARRIER_INIT(ctrl, 1); MBARRIER_INIT(ctrl+8, 1); }
    __syncthreads();

    const int cx = h * 64;
    auto issue = [&](int buf, int t0) {
        uint32_t fb = ctrl + 8*buf;
        MBARRIER_EXPECT_TX(fb, (uint32_t)(SBUF*4));
        uint32_t dst = smb + buf*SBUF*4;
        int cy = b*Tz + t0;
        TMA2D(dst + 0*STB*64*4, &mR,  cx, cy, fb);
        TMA2D(dst + 1*STB*64*4, &mW,  cx, cy, fb);
        TMA2D(dst + 2*STB*64*4, &mK,  cx, cy, fb);
        TMA2D(dst + 3*STB*64*4, &mAA, cx, cy, fb);
        TMA2D(dst + 4*STB*64*4, &mBB, cx, cy, fb);
        TMA2D(dst + 5*STB*64*4, &mV,  cx, cy, fb);
    };

    if (tid == 0) { issue(0, 0); issue(1, STB); }

    u64 S2[4];                                // 8 cols as 4 f32x2
#pragma unroll
    for (int q = 0; q < 4; q++) S2[q] = 0ULL;

    float* obase = o + (size_t)b * Tz * Cz + h * 64;
    int ph[2] = {0, 0};
    const int NTB = Tz / STB;

    for (int tb = 0; tb < NTB; tb++) {
        const int buf = tb & 1;
        mbar_wait(ctrl + 8*buf, ph[buf]);
        ph[buf] ^= 1;
        const float* base_ = sm + buf*SBUF;

        for (int tt = 0; tt < STB; tt++) {
            const float* s_r  = base_ + 0*STB*64 + tt*64;
            const float* s_w  = base_ + 1*STB*64 + tt*64;
            const float* s_k  = base_ + 2*STB*64 + tt*64;
            const float* s_aa = base_ + 3*STB*64 + tt*64;
            const float* s_bb = base_ + 4*STB*64 + tt*64;
            const float* s_v  = base_ + 5*STB*64 + tt*64;

            // sa_i = S[i,:] . aa  (partial over 8 cols, reduce across 8 lanes)
            ulonglong2 a01 = *(const ulonglong2*)&s_aa[jb];
            ulonglong2 a23 = *(const ulonglong2*)&s_aa[jb + 4];
            u64 p0 = ffma2(S2[0], a01.x, 0ULL);
            p0 = ffma2(S2[1], a01.y, p0);
            u64 p1 = ffma2(S2[2], a23.x, 0ULL);
            p1 = ffma2(S2[3], a23.y, p1);
            float2 f0 = unpack2(p0), f1 = unpack2(p1);
            float sa = (f0.x + f0.y) + (f1.x + f1.y);
            sa += __shfl_xor_sync(0xffffffffu, sa, 1);
            sa += __shfl_xor_sync(0xffffffffu, sa, 2);
            sa += __shfl_xor_sync(0xffffffffu, sa, 4);
            const u64 sa2 = pack2(sa, sa);
            const float vi = s_v[i];
            const u64 vi2 = pack2(vi, vi);

            // S = S*w + sa*bb + vi*k ; out = S . r (partial)
            ulonglong2 w01 = *(const ulonglong2*)&s_w [jb];
            ulonglong2 w23 = *(const ulonglong2*)&s_w [jb + 4];
            ulonglong2 b01 = *(const ulonglong2*)&s_bb[jb];
            ulonglong2 b23 = *(const ulonglong2*)&s_bb[jb + 4];
            ulonglong2 k01 = *(const ulonglong2*)&s_k [jb];
            ulonglong2 k23 = *(const ulonglong2*)&s_k [jb + 4];
            ulonglong2 r01 = *(const ulonglong2*)&s_r [jb];
            ulonglong2 r23 = *(const ulonglong2*)&s_r [jb + 4];

            u64 o0 = 0ULL, o1 = 0ULL;
            S2[0] = ffma2(S2[0], w01.x, ffma2(sa2, b01.x, fmul2(vi2, k01.x)));
            o0    = ffma2(S2[0], r01.x, o0);
            S2[1] = ffma2(S2[1], w01.y, ffma2(sa2, b01.y, fmul2(vi2, k01.y)));
            o0    = ffma2(S2[1], r01.y, o0);
            S2[2] = ffma2(S2[2], w23.x, ffma2(sa2, b23.x, fmul2(vi2, k23.x)));
            o1    = ffma2(S2[2], r23.x, o1);
            S2[3] = ffma2(S2[3], w23.y, ffma2(sa2, b23.y, fmul2(vi2, k23.y)));
            o1    = ffma2(S2[3], r23.y, o1);

            float2 q0 = unpack2(o0), q1 = unpack2(o1);
            float out = (q0.x + q0.y) + (q1.x + q1.y);
            out += __shfl_xor_sync(0xffffffffu, out, 1);
            out += __shfl_xor_sync(0xffffffffu, out, 2);
            out += __shfl_xor_sync(0xffffffffu, out, 4);
            if (jq == 0) obase[(size_t)(tb*STB + tt) * Cz + i] = out;
        }

        __syncthreads();   // all threads done reading buf
        if (tid == 0 && tb + 2 < NTB) issue(buf, (tb + 2) * STB);
    }
}

// ---------------- groupnorm + rk bonus + gate -> fp16 ----------------
__global__ void post_kernel(const float* __restrict__ rk,
                            const float* __restrict__ gamma, const float* __restrict__ beta)
{
    int gw   = (blockIdx.x * blockDim.x + threadIdx.x) >> 5;
    int lane = threadIdx.x & 31;
    if (gw >= BTz * Hz) return;
    int bt = gw / Hz, h = gw % Hz;
    int c0 = h * 64 + lane, c1 = c0 + 32;
    size_t base = (size_t)bt * Cz;
    float o0 = g_o[base + c0], o1 = g_o[base + c1];
    float s1 = o0 + o1;
    float s2 = o0*o0 + o1*o1;
    float r0 = g_r[base + c0], r1 = g_r[base + c1];
    float k0 = g_k[base + c0], k1 = g_k[base + c1];
    float bon = r0 * k0 * rk[h * 64 + lane] + r1 * k1 * rk[h * 64 + lane + 32];
#pragma unroll
    for (int m = 16; m > 0; m >>= 1) {
        s1  += __shfl_xor_sync(0xffffffffu, s1,  m);
        s2  += __shfl_xor_sync(0xffffffffu, s2,  m);
        bon += __shfl_xor_sync(0xffffffffu, bon, m);
    }
    float mu   = s1 * (1.f / 64.f);
    float var  = s2 * (1.f / 64.f) - mu * mu;
    float rstd = rsqrtf(var + 0.00064f);
    float v0 = g_v[base + c0], v1 = g_v[base + c1];
    float y0 = ((o0 - mu) * rstd * gamma[c0] + beta[c0] + bon * v0) * g_g[base + c0];
    float y1 = ((o1 - mu) * rstd * gamma[c1] + beta[c1] + bon * v1) * g_g[base + c1];
    g_yg[base + c0] = __float2half_rn(y0);
    g_yg[base + c1] = __float2half_rn(y1);
}

// ---------------- host: tensormap builders ----------------
typedef CUresult (*PFN_encode)(CUtensorMap*, CUtensorMapDataType, cuuint32_t, void*,
                               const cuuint64_t*, const cuuint64_t*, const cuuint32_t*,
                               const cuuint32_t*, CUtensorMapInterleave, CUtensorMapSwizzle,
                               CUtensorMapL2promotion, CUtensorMapFloatOOBfill);

static void make_map(PFN_encode enc, CUtensorMap* m, const void* base,
                     unsigned long long d0, unsigned long long d1,
                     unsigned long long stride1B, unsigned box0, unsigned box1)
{
    cuuint64_t dims[2]    = { d0, d1 };
    cuuint64_t strides[1] = { stride1B };
    cuuint32_t box[2]     = { box0, box1 };
    cuuint32_t es[2]      = { 1, 1 };
    enc(m, CU_TENSOR_MAP_DATA_TYPE_FLOAT16, 2, (void*)base, dims, strides, box, es,
        CU_TENSOR_MAP_INTERLEAVE_NONE, CU_TENSOR_MAP_SWIZZLE_128B,
        CU_TENSOR_MAP_L2_PROMOTION_L2_128B, CU_TENSOR_MAP_FLOAT_OOB_FILL_NONE);
}

static void make_map_f32(PFN_encode enc, CUtensorMap* m, const void* base,
                         unsigned long long d0, unsigned long long d1,
                         unsigned long long stride1B, unsigned box0, unsigned box1)
{
    cuuint64_t dims[2]    = { d0, d1 };
    cuuint64_t strides[1] = { stride1B };
    cuuint32_t box[2]     = { box0, box1 };
    cuuint32_t es[2]      = { 1, 1 };
    enc(m, CU_TENSOR_MAP_DATA_TYPE_FLOAT32, 2, (void*)base, dims, strides, box, es,
        CU_TENSOR_MAP_INTERLEAVE_NONE, CU_TENSOR_MAP_SWIZZLE_NONE,
        CU_TENSOR_MAP_L2_PROMOTION_L2_128B, CU_TENSOR_MAP_FLOAT_OOB_FILL_NONE);
}

#define SMEM_128 (2048 + 2*(128*128 + 2*128*128))
#define SMEM_64  (2048 + 2*(128*128 + 2*64*128))

// ---------------- launch ----------------
extern "C" void kernel_launch(void* const* d_in, const int* in_sizes, int n_in,
                              void* d_out, int out_size)
{
    const float* x    = (const float*)d_in[0];
    const float* x_r  = (const float*)d_in[1];
    const float* x_w  = (const float*)d_in[2];
    const float* x_k  = (const float*)d_in[3];
    const float* x_v  = (const float*)d_in[4];
    const float* x_a  = (const float*)d_in[5];
    const float* x_g  = (const float*)d_in[6];
    const float* w0   = (const float*)d_in[7];
    const float* w1   = (const float*)d_in[8];
    const float* w2   = (const float*)d_in[9];
    const float* a0   = (const float*)d_in[10];
    const float* a1   = (const float*)d_in[11];
    const float* a2   = (const float*)d_in[12];
    const float* g1   = (const float*)d_in[16];
    const float* g2   = (const float*)d_in[17];
    const float* k_k  = (const float*)d_in[18];
    const float* k_a  = (const float*)d_in[19];
    const float* r_k  = (const float*)d_in[20];
    const float* Wr   = (const float*)d_in[21];
    const float* Wk   = (const float*)d_in[22];
    const float* Wv   = (const float*)d_in[23];
    const float* Wo   = (const float*)d_in[24];
    const float* lg   = (const float*)d_in[25];
    const float* lb   = (const float*)d_in[26];

    void *pr, *pk, *pv, *pwd, *pa, *pg, *paa, *pbb, *po;
    void *px6, *pyg, *phid, *pwh, *pwl;
    cudaGetSymbolAddress(&pr,  g_r);   cudaGetSymbolAddress(&pk,  g_k);
    cudaGetSymbolAddress(&pv,  g_v);   cudaGetSymbolAddress(&pwd, g_wd);
    cudaGetSymbolAddress(&pa,  g_a);   cudaGetSymbolAddress(&pg,  g_g);
    cudaGetSymbolAddress(&paa, g_aa);  cudaGetSymbolAddress(&pbb, g_bb);
    cudaGetSymbolAddress(&po,  g_o);
    cudaGetSymbolAddress(&px6, g_x6);  cudaGetSymbolAddress(&pyg, g_yg);
    cudaGetSymbolAddress(&phid, g_hid);
    cudaGetSymbolAddress(&pwh, g_wh);  cudaGetSymbolAddress(&pwl, g_wl);

    float *rb = (float*)pr, *kb = (float*)pk, *vb = (float*)pv, *wd = (float*)pwd;
    float *ab = (float*)pa, *gb = (float*)pg, *aab = (float*)paa, *bbb = (float*)pbb;
    float *ob = (float*)po;
    f16 *x6 = (f16*)px6, *yg = (f16*)pyg, *hid = (f16*)phid;
    f16 *wh = (f16*)pwh, *wl = (f16*)pwl;

    const size_t S = (size_t)BTz * Cz;

    cudaFuncSetAttribute(tc_gemm6<128>, cudaFuncAttributeMaxDynamicSharedMemorySize, SMEM_128);
    cudaFuncSetAttribute(tc_gemm3h<64>, cudaFuncAttributeMaxDynamicSharedMemorySize, SMEM_64);
    cudaFuncSetAttribute(scan_kernel,   cudaFuncAttributeMaxDynamicSharedMemorySize, SCAN_SMEM);

    PFN_encode enc = nullptr;
    cudaDriverEntryPointQueryResult qres;
    cudaGetDriverEntryPoint("cuTensorMapEncodeTiled", (void**)&enc,
                            cudaEnableDefault, &qres);

    // 1. transpose+split all weights into the pool
    TJobs jb;
    jb.src[0]=Wr; jb.src[1]=Wk; jb.src[2]=Wv; jb.src[3]=Wo;
    jb.src[4]=w1; jb.src[5]=a1; jb.src[6]=g1;
    jb.src[7]=w2; jb.src[8]=a2; jb.src[9]=g2;
    jb.dstoff[0]=O_Wr; jb.dstoff[1]=O_Wk; jb.dstoff[2]=O_Wv; jb.dstoff[3]=O_Wo;
    jb.dstoff[4]=O_L1; jb.dstoff[5]=O_L1+64*Cz; jb.dstoff[6]=O_L1+128*Cz;
    jb.dstoff[7]=O_W2T; jb.dstoff[8]=O_A2T; jb.dstoff[9]=O_G2T;
    jb.K[0]=jb.K[1]=jb.K[2]=jb.K[3]=Cz; jb.K[4]=jb.K[5]=jb.K[6]=Cz;
    jb.K[7]=64; jb.K[8]=64; jb.K[9]=128;
    jb.N[0]=jb.N[1]=jb.N[2]=jb.N[3]=Cz; jb.N[4]=64; jb.N[5]=64; jb.N[6]=128;
    jb.N[7]=Cz; jb.N[8]=Cz; jb.N[9]=Cz;
    int tb = 0;
    for (int j = 0; j < 10; j++) { jb.tbase[j] = tb; tb += (jb.K[j]/32)*(jb.N[j]/32); }
    jb.tbase[10] = tb;
    tsplit_kernel<<<tb, dim3(32,8)>>>(jb, wh, wl);

    // 2. token shift + mix
    mix_kernel<<<(BTz*Cz/4 + 255)/256, 256>>>(x, x_r, x_w, x_k, x_v, x_a, x_g, x6);

    CUtensorMap A0, A1, A2, B0h, B1h, B2h, B0l, B1l, B2l;

    // 3. fused LoRA stage-1: z0 hw=tanh(xw@w1), z1 ha=xa@a1, z2 hg=sig(xg@g1)
    make_map(enc, &A0,  x6 + 1*S, Cz, BTz, Cz*2, 64, 128);
    make_map(enc, &A1,  x6 + 4*S, Cz, BTz, Cz*2, 64, 128);
    make_map(enc, &A2,  x6 + 5*S, Cz, BTz, Cz*2, 64, 128);
    make_map(enc, &B0h, wh + O_L1,          Cz, 64,  Cz*2, 64, 64);
    make_map(enc, &B1h, wh + O_L1 + 64*Cz,  Cz, 64,  Cz*2, 64, 64);
    make_map(enc, &B2h, wh + O_L1 + 128*Cz, Cz, 128, Cz*2, 64, 64);
    make_map(enc, &B0l, wl + O_L1,          Cz, 64,  Cz*2, 64, 64);
    make_map(enc, &B1l, wl + O_L1 + 64*Cz,  Cz, 64,  Cz*2, 64, 64);
    make_map(enc, &B2l, wl + O_L1 + 128*Cz, Cz, 128, Cz*2, 64, 64);
    tc_gemm3h<64><<<dim3(2, BTz/128, 3), 256, SMEM_64>>>(
        A0, A1, A2, B0h, B1h, B2h, B0l, B1l, B2l,
        hid, hid + 64, hid + 128,
        256, 1, 0, 2, 1, 1, 2);

    // 4. ONE launch: r, k, v projections + LoRA stage-2 (6 jobs)
    G6 g6;
    make_map(enc, &g6.A[0], x6 + 0*S, Cz, BTz, Cz*2, 64, 128);
    make_map(enc, &g6.A[1], x6 + 2*S, Cz, BTz, Cz*2, 64, 128);
    make_map(enc, &g6.A[2], x6 + 3*S, Cz, BTz, Cz*2, 64, 128);
    make_map(enc, &g6.A[3], hid,       64,  BTz, 256*2, 64, 128);
    make_map(enc, &g6.A[4], hid + 64,  64,  BTz, 256*2, 64, 128);
    make_map(enc, &g6.A[5], hid + 128, 128, BTz, 256*2, 64, 128);
    make_map(enc, &g6.Bh[0], wh + O_Wr,  Cz,  Cz, Cz*2,  64, 128);
    make_map(enc, &g6.Bh[1], wh + O_Wk,  Cz,  Cz, Cz*2,  64, 128);
    make_map(enc, &g6.Bh[2], wh + O_Wv,  Cz,  Cz, Cz*2,  64, 128);
    make_map(enc, &g6.Bh[3], wh + O_W2T, 64,  Cz, 64*2,  64, 128);
    make_map(enc, &g6.Bh[4], wh + O_A2T, 64,  Cz, 64*2,  64, 128);
    make_map(enc, &g6.Bh[5], wh + O_G2T, 128, Cz, 128*2, 64, 128);
    make_map(enc, &g6.Bl[0], wl + O_Wr,  Cz,  Cz, Cz*2,  64, 128);
    make_map(enc, &g6.Bl[1], wl + O_Wk,  Cz,  Cz, Cz*2,  64, 128);
    make_map(enc, &g6.Bl[2], wl + O_Wv,  Cz,  Cz, Cz*2,  64, 128);
    make_map(enc, &g6.Bl[3], wl + O_W2T, 64,  Cz, 64*2,  64, 128);
    make_map(enc, &g6.Bl[4], wl + O_A2T, 64,  Cz, 64*2,  64, 128);
    make_map(enc, &g6.Bl[5], wl + O_G2T, 128, Cz, 128*2, 64, 128);
    g6.K[0] = Cz; g6.K[1] = Cz; g6.K[2] = Cz; g6.K[3] = 64; g6.K[4] = 64; g6.K[5] = 128;
    g6.C[0] = rb; g6.C[1] = kb; g6.C[2] = vb; g6.C[3] = wd; g6.C[4] = ab; g6.C[5] = gb;
    g6.bias[0] = nullptr; g6.bias[1] = nullptr; g6.bias[2] = nullptr;
    g6.bias[3] = w0; g6.bias[4] = a0; g6.bias[5] = nullptr;
    g6.epi[0] = 0; g6.epi[1] = 0; g6.epi[2] = 0; g6.epi[3] = 3; g6.epi[4] = 2; g6.epi[5] = 0;
    tc_gemm6<128><<<dim3(8, BTz/128, 6), 256, SMEM_128>>>(g6, Cz);

    // 5. kk normalize / aa / bb / k update (parallel)
    prep_kernel<<<BTz*Hz/8, 256>>>(k_k, k_a);

    // 6. sequential scan (TMA-batched, row-split across RSPLIT blocks per head)
    {
        CUtensorMap sR, sW, sK, sAA, sBB, sV;
        make_map_f32(enc, &sR,  rb,  Cz, BTz, Cz*4, 64, STB);
        make_map_f32(enc, &sW,  wd,  Cz, BTz, Cz*4, 64, STB);
        make_map_f32(enc, &sK,  kb,  Cz, BTz, Cz*4, 64, STB);
        make_map_f32(enc, &sAA, aab, Cz, BTz, Cz*4, 64, STB);
        make_map_f32(enc, &sBB, bbb, Cz, BTz, Cz*4, 64, STB);
        make_map_f32(enc, &sV,  vb,  Cz, BTz, Cz*4, 64, STB);
        scan_kernel<<<dim3(Bz*Hz, RSPLIT), 256, SCAN_SMEM>>>(sR, sW, sK, sAA, sBB, sV, ob);
    }

    // 7. groupnorm + bonus + gate -> yg fp16
    post_kernel<<<BTz*Hz/8, 256>>>(r_k, lg, lb);

    // 8. output projection (1 job)
    G6 go;
    make_map(enc, &go.A[0],  yg, Cz, BTz, Cz*2, 64, 128);
    make_map(enc, &go.Bh[0], wh + O_Wo, Cz, Cz, Cz*2, 64, 128);
    make_map(enc, &go.Bl[0], wl + O_Wo, Cz, Cz, Cz*2, 64, 128);
    for (int z = 1; z < 6; z++) { go.A[z] = go.A[0]; go.Bh[z] = go.Bh[0]; go.Bl[z] = go.Bl[0]; }
    for (int z = 0; z < 6; z++) { go.K[z] = Cz; go.C[z] = (float*)d_out; go.bias[z] = nullptr; go.epi[z] = 0; }
    tc_gemm6<128><<<dim3(8, BTz/128, 1), 256, SMEM_128>>>(go, Cz);

    // 9. v_first if expected
    if (out_size >= 2 * BTz * Cz) {
        cudaMemcpyAsync((float*)d_out + S, vb, sizeof(float) * S, cudaMemcpyDeviceToDevice);
    }
}

// round 17
// speedup vs baseline: 2.0175x; 1.1164x over previous
#include <cuda_runtime.h>
#include <cuda.h>
#include <cuda_bf16.h>
#include <cuda_fp16.h>
#include <cstdint>
#include <math.h>

#define Bz   4
#define Tz   1024
#define Cz   1024
#define Hz   16
#define BTz  (Bz*Tz)

typedef __half  f16;
typedef __half2 f162;
typedef unsigned long long u64;

// ---------------- scratch (device globals; no allocation allowed) ----------------
__device__ float g_r [BTz*Cz], g_k [BTz*Cz], g_v [BTz*Cz], g_wd[BTz*Cz];
__device__ float g_a [BTz*Cz], g_g [BTz*Cz], g_aa[BTz*Cz], g_bb[BTz*Cz], g_o [BTz*Cz];

__device__ __align__(256) f16 g_x6[6*BTz*Cz];     // mixed streams, fp16
__device__ __align__(256) f16 g_yg[BTz*Cz];       // (gn(o)+bonus)*g fp16
// LoRA hidden pool [BTz, 256]: cols 0-63 decay, 64-127 a, 128-255 g (fp16)
__device__ __align__(256) f16 g_hid[BTz*256];

// weight pool: all matrices stored TRANSPOSED [N, K] row-major, fp16
#define O_Wr 0
#define O_Wk (Cz*Cz)
#define O_Wv (2*Cz*Cz)
#define O_Wo (3*Cz*Cz)
#define O_L1 (4*Cz*Cz)                  // [256, 1024]: w1t 0-63, a1t 64-127, g1t 128-255
#define O_W2T (O_L1 + 256*Cz)           // [1024, 64]
#define O_A2T (O_W2T + Cz*64)           // [1024, 64]
#define O_G2T (O_A2T + Cz*64)           // [1024, 128]
#define WPOOL (O_G2T + Cz*128)
__device__ __align__(256) f16 g_wh[WPOOL];

// ---------------- helpers ----------------
__device__ __forceinline__ uint32_t su32(const void* p) {
    return (uint32_t)__cvta_generic_to_shared(p);
}
__device__ __forceinline__ void ldsm4(uint32_t& a0, uint32_t& a1, uint32_t& a2, uint32_t& a3, uint32_t addr) {
    asm volatile("ldmatrix.sync.aligned.m8n8.x4.shared.b16 {%0,%1,%2,%3},[%4];"
                 : "=r"(a0), "=r"(a1), "=r"(a2), "=r"(a3) : "r"(addr));
}
__device__ __forceinline__ void mma16816(float* c, const uint32_t* a, const uint32_t* b) {
    asm volatile("mma.sync.aligned.m16n8k16.row.col.f32.f16.f16.f32 "
                 "{%0,%1,%2,%3},{%4,%5,%6,%7},{%8,%9},{%0,%1,%2,%3};"
                 : "+f"(c[0]), "+f"(c[1]), "+f"(c[2]), "+f"(c[3])
                 : "r"(a[0]), "r"(a[1]), "r"(a[2]), "r"(a[3]), "r"(b[0]), "r"(b[1]));
}
__device__ __forceinline__ u64 ffma2(u64 a, u64 b, u64 c) {
    u64 d; asm("fma.rn.f32x2 %0,%1,%2,%3;" : "=l"(d) : "l"(a), "l"(b), "l"(c)); return d;
}
__device__ __forceinline__ u64 fmul2(u64 a, u64 b) {
    u64 d; asm("mul.rn.f32x2 %0,%1,%2;" : "=l"(d) : "l"(a), "l"(b)); return d;
}
__device__ __forceinline__ u64 pack2(float x, float y) {
    u64 d; asm("mov.b64 %0,{%1,%2};" : "=l"(d) : "f"(x), "f"(y)); return d;
}
__device__ __forceinline__ float2 unpack2(u64 a) {
    float x, y; asm("mov.b64 {%0,%1},%2;" : "=f"(x), "=f"(y) : "l"(a)); return make_float2(x, y);
}

// ---- mbarrier / TMA ----
#define MBARRIER_INIT(addr, cnt) \
    asm volatile("mbarrier.init.shared.b64 [%0], %1;" :: "r"((uint32_t)(addr)), "r"((uint32_t)(cnt)) : "memory")
#define MBARRIER_EXPECT_TX(addr, bytes) \
    asm volatile("mbarrier.arrive.expect_tx.shared.b64 _, [%0], %1;" :: "r"((uint32_t)(addr)), "r"((uint32_t)(bytes)) : "memory")
#define TMA2D(dst, map, cx, cy, mbar) \
    asm volatile("cp.async.bulk.tensor.2d.shared::cta.global.tile.mbarrier::complete_tx::bytes [%0],[%1,{%2,%3}],[%4];" \
        :: "r"((uint32_t)(dst)), "l"(map), "r"((int)(cx)), "r"((int)(cy)), "r"((uint32_t)(mbar)) : "memory")

__device__ __forceinline__ void mbar_wait(uint32_t addr, int phase) {
    asm volatile(
        "{\n\t.reg .pred P1;\n\t"
        "WAIT_LOOP_%=:\n\t"
        "mbarrier.try_wait.parity.shared.b64 P1, [%0], %1, 0x989680;\n\t"
        "@P1 bra.uni WAIT_DONE_%=;\n\t"
        "bra.uni WAIT_LOOP_%=;\n\t"
        "WAIT_DONE_%=:\n\t}"
        :: "r"(addr), "r"((uint32_t)phase) : "memory");
}

// ---------------- transpose + convert: W[K,N] fp32 -> pool[N,K] fp16 ----------------
struct TJobs { const float* src[10]; int dstoff[10]; int K[10]; int N[10]; int tbase[11]; };

__global__ void tsplit_kernel(TJobs jb, f16* __restrict__ hi)
{
    __shared__ float s[32][33];
    int bid = blockIdx.x;
    int j = 0;
#pragma unroll
    for (int q = 1; q < 10; q++) if (bid >= jb.tbase[q]) j = q;
    int tl = bid - jb.tbase[j];
    int K = jb.K[j], N = jb.N[j];
    int ntn = N >> 5;
    int tn = tl % ntn, tk = tl / ntn;
    const float* src = jb.src[j];
    const int tid = threadIdx.x;        // 256 threads
    // load 32(k) x 32(n) tile, coalesced on n
#pragma unroll
    for (int i = 0; i < 4; i++) {
        int idx = tid + i*256;
        int r = idx >> 5, c = idx & 31;
        s[r][c] = src[(size_t)(tk*32 + r) * N + tn*32 + c];
    }
    __syncthreads();
    // store transposed: dst[n, k] fp16, f162-vectorized on k
#pragma unroll
    for (int i = 0; i < 2; i++) {
        int idx = tid + i*256;
        int n = idx >> 4, kp = idx & 15;
        float v0 = s[kp*2][n], v1 = s[kp*2+1][n];
        f162 hv = __floats2half2_rn(v0, v1);
        size_t d = (size_t)jb.dstoff[j] + (size_t)(tn*32 + n) * K + tk*32 + kp*2;
        *(f162*)&hi[d] = hv;
    }
}

// ---------------- token shift + 6-way mix, emitting fp16 ----------------
__global__ void mix_kernel(const float* __restrict__ x,
                           const float* __restrict__ mr, const float* __restrict__ mw,
                           const float* __restrict__ mk, const float* __restrict__ mv,
                           const float* __restrict__ ma, const float* __restrict__ mg,
                           f16* __restrict__ xo)
{
    int idx = blockIdx.x * blockDim.x + threadIdx.x;     // float4 index
    const int total = BTz * Cz / 4;
    if (idx >= total) return;
    int c4 = idx % (Cz / 4);
    int bt = idx / (Cz / 4);
    int t  = bt % Tz;
    const float4* x4 = (const float4*)x;
    float4 cur = x4[idx];
    float4 prev = make_float4(0.f, 0.f, 0.f, 0.f);
    if (t > 0) prev = x4[idx - Cz / 4];
    float4 xx = make_float4(prev.x - cur.x, prev.y - cur.y, prev.z - cur.z, prev.w - cur.w);
    int c = c4 * 4;
    const float* ms[6] = { mr, mw, mk, mv, ma, mg };
#pragma unroll
    for (int s = 0; s < 6; s++) {
        float4 mm = *(const float4*)(ms[s] + c);
        f162 h0 = __floats2half2_rn(cur.x + xx.x * mm.x, cur.y + xx.y * mm.y);
        f162 h1 = __floats2half2_rn(cur.z + xx.z * mm.z, cur.w + xx.w * mm.w);
        uint2 h; h.x = *(uint32_t*)&h0; h.y = *(uint32_t*)&h1;
        ((uint2*)(xo + (size_t)s * BTz * Cz))[idx] = h;
    }
}

// ---------------- epilogue ----------------
__device__ __forceinline__ float apply_epi_rt(float acc, float b, int epi)
{
    float pre = acc + b;
    if (epi == 0) return pre;
    if (epi == 1) return tanhf(pre);
    if (epi == 2) return 1.f / (1.f + expf(-pre));
    float sp = (pre > -30.f) ? log1pf(expf(-pre)) : -pre;   // softplus(-pre)
    return expf(-expf(-sp - 0.5f));
}

// ---------------- 6-job TMA + mma.sync GEMM: C = A*B (fp16, fp32 acc) ----------------
struct G6 {
    CUtensorMap A[6], Bh[6];
    int K[6];
    float* C[6];
    const float* bias[6];
    int epi[6];
};

template<int BN>
__global__ __launch_bounds__(256, 2)
void tc_gemm6(const __grid_constant__ G6 jobs, int ldc)
{
    constexpr int BM = 128;
    constexpr int ATILE = BM*128;              // 16KB
    constexpr int BTILE = BN*128;
    constexpr int STAGE = ATILE + BTILE;
    constexpr int NSTG = 3;
    constexpr int WM = 64;
    constexpr int WN = 32;
    constexpr int MFR = WM/16, NFR = WN/8;

    const int z = blockIdx.z;
    const CUtensorMap* pA  = &jobs.A[z];
    const CUtensorMap* pBh = &jobs.Bh[z];
    const int K   = jobs.K[z];
    float* C      = jobs.C[z];
    const float* bias = jobs.bias[z];
    const int epi = jobs.epi[z];

    extern __shared__ __align__(1024) char dsm[];
    uint32_t raw  = su32(dsm);
    uint32_t ctrl = (raw + 1023u) & ~1023u;
    uint32_t tiles = ctrl + 1024;

    const int tid = threadIdx.x, lane = tid & 31, warp = tid >> 5;
    const int wN = warp % (BN/WN), wM = warp / (BN/WN);
    const int row0 = blockIdx.y * BM, col0 = blockIdx.x * BN;
    const int T = K >> 6;

    if (tid == 0) {
#pragma unroll
        for (int s = 0; s < NSTG; s++) MBARRIER_INIT(ctrl + 16 + 8*s, 1);
    }
    __syncthreads();

    float acc[MFR][NFR][4];
#pragma unroll
    for (int i = 0; i < MFR; i++)
#pragma unroll
        for (int j = 0; j < NFR; j++)
#pragma unroll
            for (int q = 0; q < 4; q++) acc[i][j][q] = 0.f;

    const uint32_t swm = (uint32_t)((lane & 7) << 4);
    uint32_t aRow[MFR], bRow[NFR/2];
#pragma unroll
    for (int fm = 0; fm < MFR; fm++)
        aRow[fm] = (uint32_t)((wM*WM + fm*16 + (lane & 15)) * 128);
#pragma unroll
    for (int p = 0; p < NFR/2; p++)
        bRow[p] = (uint32_t)((wN*WN + p*16 + (lane & 7) + ((lane >> 4) << 3)) * 128);
    const uint32_t aColB = (uint32_t)((lane >> 4) * 16);
    const uint32_t bColB = (uint32_t)(((lane >> 3) & 1) * 16);

    auto issue_stage = [&](int s, int k0) {
        uint32_t sb = tiles + s*STAGE;
        uint32_t fb = ctrl + 16 + 8*s;
        MBARRIER_EXPECT_TX(fb, (uint32_t)STAGE);
        TMA2D(sb,       pA,  k0, row0, fb);
        TMA2D(sb+ATILE, pBh, k0, col0, fb);
    };

    if (tid == 0) {
        const int npre = (T < NSTG) ? T : NSTG;
        for (int s = 0; s < npre; s++) issue_stage(s, s*64);
    }

    int ph[NSTG];
#pragma unroll
    for (int s = 0; s < NSTG; s++) ph[s] = 0;

    int sidx = 0;
    for (int t = 0; t < T; t++) {
        const int s = sidx;
        sidx++; if (sidx == NSTG) sidx = 0;
        mbar_wait(ctrl + 16 + 8*s, ph[s]);
        ph[s] ^= 1;
        const uint32_t aB = tiles + s*STAGE;
        const uint32_t bH = aB + ATILE;
#pragma unroll
        for (int kk = 0; kk < 4; kk++) {
            const uint32_t aC = (uint32_t)(kk*32) + aColB;
            const uint32_t bC = (uint32_t)(kk*32) + bColB;
            uint32_t Af[MFR][4], Bf[NFR][2];
#pragma unroll
            for (int fm = 0; fm < MFR; fm++) {
                uint32_t off = aRow[fm] + (aC ^ swm);
                ldsm4(Af[fm][0], Af[fm][1], Af[fm][2], Af[fm][3], aB + off);
            }
#pragma unroll
            for (int p = 0; p < NFR/2; p++) {
                uint32_t off = bRow[p] + (bC ^ swm);
                uint32_t t0, t1, t2, t3;
                ldsm4(t0, t1, t2, t3, bH + off);
                Bf[2*p][0] = t0; Bf[2*p][1] = t1; Bf[2*p+1][0] = t2; Bf[2*p+1][1] = t3;
            }
#pragma unroll
            for (int fm = 0; fm < MFR; fm++)
#pragma unroll
                for (int fn = 0; fn < NFR; fn++)
                    mma16816(acc[fm][fn], Af[fm], Bf[fn]);
        }
        __syncthreads();
        if (tid == 0 && t + NSTG < T) issue_stage(s, (t + NSTG) * 64);
    }

    // epilogue
#pragma unroll
    for (int fm = 0; fm < MFR; fm++) {
        int r = row0 + wM*WM + fm*16 + (lane >> 2);
#pragma unroll
        for (int fn = 0; fn < NFR; fn++) {
            int c = col0 + wN*WN + fn*8 + 2*(lane & 3);
            float b0 = bias ? bias[c] : 0.f;
            float b1 = bias ? bias[c+1] : 0.f;
            float x0 = apply_epi_rt(acc[fm][fn][0], b0, epi);
            float x1 = apply_epi_rt(acc[fm][fn][1], b1, epi);
            float x2 = apply_epi_rt(acc[fm][fn][2], b0, epi);
            float x3 = apply_epi_rt(acc[fm][fn][3], b1, epi);
            *(float2*)&C[(size_t)r*ldc + c]     = make_float2(x0, x1);
            *(float2*)&C[(size_t)(r+8)*ldc + c] = make_float2(x2, x3);
        }
    }
}

// ---------------- 3-job LoRA stage-1 GEMM (BN=64, fp16 out) ----------------
template<int BN>
__global__ __launch_bounds__(256, 2)
void tc_gemm3h(const __grid_constant__ CUtensorMap mA0,
               const __grid_constant__ CUtensorMap mA1,
               const __grid_constant__ CUtensorMap mA2,
               const __grid_constant__ CUtensorMap mB0h,
               const __grid_constant__ CUtensorMap mB1h,
               const __grid_constant__ CUtensorMap mB2h,
               f16* H0, f16* H1, f16* H2,
               int ldc, int epi0, int epi1, int epi2,
               int xc0, int xc1, int xc2)
{
    constexpr int BM = 128;
    constexpr int ATILE = BM*128;
    constexpr int BTILE = BN*128;
    constexpr int STAGE = ATILE + BTILE;
    constexpr int NSTG = 3;
    constexpr int WM = 32, WN = 32;
    constexpr int MFR = WM/16, NFR = WN/8;

    const int z = blockIdx.z;
    const int xcnt = (z == 0) ? xc0 : (z == 1) ? xc1 : xc2;
    if ((int)blockIdx.x >= xcnt) return;

    const CUtensorMap* pA  = (z == 0) ? &mA0  : (z == 1) ? &mA1  : &mA2;
    const CUtensorMap* pBh = (z == 0) ? &mB0h : (z == 1) ? &mB1h : &mB2h;
    f16* Ch = (z == 0) ? H0 : (z == 1) ? H1 : H2;
    const int epi = (z == 0) ? epi0 : (z == 1) ? epi1 : epi2;
    const int K = Cz;

    extern __shared__ __align__(1024) char dsm[];
    uint32_t raw  = su32(dsm);
    uint32_t ctrl = (raw + 1023u) & ~1023u;
    uint32_t tiles = ctrl + 1024;

    const int tid = threadIdx.x, lane = tid & 31, warp = tid >> 5;
    const int wN = warp % (BN/WN), wM = warp / (BN/WN);
    const int row0 = blockIdx.y * BM, col0 = blockIdx.x * BN;
    const int T = K >> 6;

    if (tid == 0) {
#pragma unroll
        for (int s = 0; s < NSTG; s++) MBARRIER_INIT(ctrl + 16 + 8*s, 1);
    }
    __syncthreads();

    float acc[MFR][NFR][4];
#pragma unroll
    for (int i = 0; i < MFR; i++)
#pragma unroll
        for (int j = 0; j < NFR; j++)
#pragma unroll
            for (int q = 0; q < 4; q++) acc[i][j][q] = 0.f;

    const uint32_t swm = (uint32_t)((lane & 7) << 4);
    uint32_t aRow[MFR], bRow[NFR/2];
#pragma unroll
    for (int fm = 0; fm < MFR; fm++)
        aRow[fm] = (uint32_t)((wM*WM + fm*16 + (lane & 15)) * 128);
#pragma unroll
    for (int p = 0; p < NFR/2; p++)
        bRow[p] = (uint32_t)((wN*WN + p*16 + (lane & 7) + ((lane >> 4) << 3)) * 128);
    const uint32_t aColB = (uint32_t)((lane >> 4) * 16);
    const uint32_t bColB = (uint32_t)(((lane >> 3) & 1) * 16);

    auto issue_stage = [&](int s, int k0) {
        uint32_t sb = tiles + s*STAGE;
        uint32_t fb = ctrl + 16 + 8*s;
        MBARRIER_EXPECT_TX(fb, (uint32_t)STAGE);
        TMA2D(sb,       pA,  k0, row0, fb);
        TMA2D(sb+ATILE, pBh, k0, col0, fb);
    };

    if (tid == 0) {
        const int npre = (T < NSTG) ? T : NSTG;
        for (int s = 0; s < npre; s++) issue_stage(s, s*64);
    }

    int ph[NSTG];
#pragma unroll
    for (int s = 0; s < NSTG; s++) ph[s] = 0;

    int sidx = 0;
    for (int t = 0; t < T; t++) {
        const int s = sidx;
        sidx++; if (sidx == NSTG) sidx = 0;
        mbar_wait(ctrl + 16 + 8*s, ph[s]);
        ph[s] ^= 1;
        const uint32_t aB = tiles + s*STAGE;
        const uint32_t bH = aB + ATILE;
#pragma unroll
        for (int kk = 0; kk < 4; kk++) {
            const uint32_t aC = (uint32_t)(kk*32) + aColB;
            const uint32_t bC = (uint32_t)(kk*32) + bColB;
            uint32_t Af[MFR][4], Bf[NFR][2];
#pragma unroll
            for (int fm = 0; fm < MFR; fm++) {
                uint32_t off = aRow[fm] + (aC ^ swm);
                ldsm4(Af[fm][0], Af[fm][1], Af[fm][2], Af[fm][3], aB + off);
            }
#pragma unroll
            for (int p = 0; p < NFR/2; p++) {
                uint32_t off = bRow[p] + (bC ^ swm);
                uint32_t t0, t1, t2, t3;
                ldsm4(t0, t1, t2, t3, bH + off);
                Bf[2*p][0] = t0; Bf[2*p][1] = t1; Bf[2*p+1][0] = t2; Bf[2*p+1][1] = t3;
            }
#pragma unroll
            for (int fm = 0; fm < MFR; fm++)
#pragma unroll
                for (int fn = 0; fn < NFR; fn++)
                    mma16816(acc[fm][fn], Af[fm], Bf[fn]);
        }
        __syncthreads();
        if (tid == 0 && t + NSTG < T) issue_stage(s, (t + NSTG) * 64);
    }

#pragma unroll
    for (int fm = 0; fm < MFR; fm++) {
        int r = row0 + wM*WM + fm*16 + (lane >> 2);
#pragma unroll
        for (int fn = 0; fn < NFR; fn++) {
            int c = col0 + wN*WN + fn*8 + 2*(lane & 3);
            float x0 = apply_epi_rt(acc[fm][fn][0], 0.f, epi);
            float x1 = apply_epi_rt(acc[fm][fn][1], 0.f, epi);
            float x2 = apply_epi_rt(acc[fm][fn][2], 0.f, epi);
            float x3 = apply_epi_rt(acc[fm][fn][3], 0.f, epi);
            f162 h0 = __floats2half2_rn(x0, x1);
            f162 h1 = __floats2half2_rn(x2, x3);
            *(f162*)&Ch[(size_t)r*ldc + c]     = h0;
            *(f162*)&Ch[(size_t)(r+8)*ldc + c] = h1;
        }
    }
}

// ---------------- kk normalize, aa, bb, k update (parallel) ----------------
__global__ void prep_kernel(const float* __restrict__ kkw, const float* __restrict__ kaw)
{
    int gw   = (blockIdx.x * blockDim.x + threadIdx.x) >> 5;
    int lane = threadIdx.x & 31;
    if (gw >= BTz * Hz) return;
    int bt = gw / Hz, h = gw % Hz;
    int c0 = h * 64 + lane, c1 = c0 + 32;
    size_t base = (size_t)bt * Cz;
    float k0 = g_k[base + c0], k1 = g_k[base + c1];
    float kk0 = k0 * kkw[c0], kk1 = k1 * kkw[c1];
    float ss = kk0*kk0 + kk1*kk1;
#pragma unroll
    for (int m = 16; m > 0; m >>= 1) ss += __shfl_xor_sync(0xffffffffu, ss, m);
    float inv = 1.f / fmaxf(sqrtf(ss), 1e-12f);
    float a0 = g_a[base + c0], a1v = g_a[base + c1];
    kk0 *= inv; kk1 *= inv;
    g_aa[base + c0] = -kk0;       g_aa[base + c1] = -kk1;
    g_bb[base + c0] = kk0 * a0;   g_bb[base + c1] = kk1 * a1v;
    g_k [base + c0] = k0 * (1.f + (a0  - 1.f) * kaw[c0]);
    g_k [base + c1] = k1 * (1.f + (a1v - 1.f) * kaw[c1]);
}

// ---------------- sequential RWKV7 scan: TMA-batched, row-split ----------------
#define STB  16
#define SBUF (6*STB*64)                       // floats per buffer
#define SCAN_SMEM (2*SBUF*4 + 64)
#define RSPLIT 2
#define RPB (64/RSPLIT)                       // 32 rows per block

__global__ __launch_bounds__(256)
void scan_kernel(const __grid_constant__ CUtensorMap mR,
                 const __grid_constant__ CUtensorMap mW,
                 const __grid_constant__ CUtensorMap mK,
                 const __grid_constant__ CUtensorMap mAA,
                 const __grid_constant__ CUtensorMap mBB,
                 const __grid_constant__ CUtensorMap mV,
                 float* __restrict__ o)
{
    const int bh = blockIdx.x;
    const int rg = blockIdx.y;
    const int b = bh / Hz, h = bh % Hz;
    const int tid = threadIdx.x;
    const int row = tid >> 3;                 // 0..31 local row
    const int i   = rg * RPB + row;           // global value-row 0..63
    const int jq  = tid & 7;
    const int jb  = jq * 8;                   // 8 cols per thread

    extern __shared__ __align__(128) float sm[];
    const uint32_t smb = su32(sm);
    const uint32_t ctrl = smb + 2*SBUF*4;

    if (tid == 0) { MBARRIER_INIT(ctrl, 1); MBARRIER_INIT(ctrl+8, 1); }
    __syncthreads();

    const int cx = h * 64;
    auto issue = [&](int buf, int t0) {
        uint32_t fb = ctrl + 8*buf;
        MBARRIER_EXPECT_TX(fb, (uint32_t)(SBUF*4));
        uint32_t dst = smb + buf*SBUF*4;
        int cy = b*Tz + t0;
        TMA2D(dst + 0*STB*64*4, &mR,  cx, cy, fb);
        TMA2D(dst + 1*STB*64*4, &mW,  cx, cy, fb);
        TMA2D(dst + 2*STB*64*4, &mK,  cx, cy, fb);
        TMA2D(dst + 3*STB*64*4, &mAA, cx, cy, fb);
        TMA2D(dst + 4*STB*64*4, &mBB, cx, cy, fb);
        TMA2D(dst + 5*STB*64*4, &mV,  cx, cy, fb);
    };

    if (tid == 0) { issue(0, 0); issue(1, STB); }

    u64 S2[4];                                // 8 cols as 4 f32x2
#pragma unroll
    for (int q = 0; q < 4; q++) S2[q] = 0ULL;

    float* obase = o + (size_t)b * Tz * Cz + h * 64;
    int ph[2] = {0, 0};
    const int NTB = Tz / STB;

    for (int tb = 0; tb < NTB; tb++) {
        const int buf = tb & 1;
        mbar_wait(ctrl + 8*buf, ph[buf]);
        ph[buf] ^= 1;
        const float* base_ = sm + buf*SBUF;

        for (int tt = 0; tt < STB; tt++) {
            const float* s_r  = base_ + 0*STB*64 + tt*64;
            const float* s_w  = base_ + 1*STB*64 + tt*64;
            const float* s_k  = base_ + 2*STB*64 + tt*64;
            const float* s_aa = base_ + 3*STB*64 + tt*64;
            const float* s_bb = base_ + 4*STB*64 + tt*64;
            const float* s_v  = base_ + 5*STB*64 + tt*64;

            ulonglong2 a01 = *(const ulonglong2*)&s_aa[jb];
            ulonglong2 a23 = *(const ulonglong2*)&s_aa[jb + 4];
            u64 p0 = ffma2(S2[0], a01.x, 0ULL);
            p0 = ffma2(S2[1], a01.y, p0);
            u64 p1 = ffma2(S2[2], a23.x, 0ULL);
            p1 = ffma2(S2[3], a23.y, p1);
            float2 f0 = unpack2(p0), f1 = unpack2(p1);
            float sa = (f0.x + f0.y) + (f1.x + f1.y);
            sa += __shfl_xor_sync(0xffffffffu, sa, 1);
            sa += __shfl_xor_sync(0xffffffffu, sa, 2);
            sa += __shfl_xor_sync(0xffffffffu, sa, 4);
            const u64 sa2 = pack2(sa, sa);
            const float vi = s_v[i];
            const u64 vi2 = pack2(vi, vi);

            ulonglong2 w01 = *(const ulonglong2*)&s_w [jb];
            ulonglong2 w23 = *(const ulonglong2*)&s_w [jb + 4];
            ulonglong2 b01 = *(const ulonglong2*)&s_bb[jb];
            ulonglong2 b23 = *(const ulonglong2*)&s_bb[jb + 4];
            ulonglong2 k01 = *(const ulonglong2*)&s_k [jb];
            ulonglong2 k23 = *(const ulonglong2*)&s_k [jb + 4];
            ulonglong2 r01 = *(const ulonglong2*)&s_r [jb];
            ulonglong2 r23 = *(const ulonglong2*)&s_r [jb + 4];

            u64 o0 = 0ULL, o1 = 0ULL;
            S2[0] = ffma2(S2[0], w01.x, ffma2(sa2, b01.x, fmul2(vi2, k01.x)));
            o0    = ffma2(S2[0], r01.x, o0);
            S2[1] = ffma2(S2[1], w01.y, ffma2(sa2, b01.y, fmul2(vi2, k01.y)));
            o0    = ffma2(S2[1], r01.y, o0);
            S2[2] = ffma2(S2[2], w23.x, ffma2(sa2, b23.x, fmul2(vi2, k23.x)));
            o1    = ffma2(S2[2], r23.x, o1);
            S2[3] = ffma2(S2[3], w23.y, ffma2(sa2, b23.y, fmul2(vi2, k23.y)));
            o1    = ffma2(S2[3], r23.y, o1);

            float2 q0 = unpack2(o0), q1 = unpack2(o1);
            float out = (q0.x + q0.y) + (q1.x + q1.y);
            out += __shfl_xor_sync(0xffffffffu, out, 1);
            out += __shfl_xor_sync(0xffffffffu, out, 2);
            out += __shfl_xor_sync(0xffffffffu, out, 4);
            if (jq == 0) obase[(size_t)(tb*STB + tt) * Cz + i] = out;
        }

        __syncthreads();
        if (tid == 0 && tb + 2 < NTB) issue(buf, (tb + 2) * STB);
    }
}

// ---------------- groupnorm + rk bonus + gate -> fp16 ----------------
__global__ void post_kernel(const float* __restrict__ rk,
                            const float* __restrict__ gamma, const float* __restrict__ beta)
{
    int gw   = (blockIdx.x * blockDim.x + threadIdx.x) >> 5;
    int lane = threadIdx.x & 31;
    if (gw >= BTz * Hz) return;
    int bt = gw / Hz, h = gw % Hz;
    int c0 = h * 64 + lane, c1 = c0 + 32;
    size_t base = (size_t)bt * Cz;
    float o0 = g_o[base + c0], o1 = g_o[base + c1];
    float s1 = o0 + o1;
    float s2 = o0*o0 + o1*o1;
    float r0 = g_r[base + c0], r1 = g_r[base + c1];
    float k0 = g_k[base + c0], k1 = g_k[base + c1];
    float bon = r0 * k0 * rk[h * 64 + lane] + r1 * k1 * rk[h * 64 + lane + 32];
#pragma unroll
    for (int m = 16; m > 0; m >>= 1) {
        s1  += __shfl_xor_sync(0xffffffffu, s1,  m);
        s2  += __shfl_xor_sync(0xffffffffu, s2,  m);
        bon += __shfl_xor_sync(0xffffffffu, bon, m);
    }
    float mu   = s1 * (1.f / 64.f);
    float var  = s2 * (1.f / 64.f) - mu * mu;
    float rstd = rsqrtf(var + 0.00064f);
    float v0 = g_v[base + c0], v1 = g_v[base + c1];
    float y0 = ((o0 - mu) * rstd * gamma[c0] + beta[c0] + bon * v0) * g_g[base + c0];
    float y1 = ((o1 - mu) * rstd * gamma[c1] + beta[c1] + bon * v1) * g_g[base + c1];
    g_yg[base + c0] = __float2half_rn(y0);
    g_yg[base + c1] = __float2half_rn(y1);
}

// ---------------- host: tensormap builders ----------------
typedef CUresult (*PFN_encode)(CUtensorMap*, CUtensorMapDataType, cuuint32_t, void*,
                               const cuuint64_t*, const cuuint64_t*, const cuuint32_t*,
                               const cuuint32_t*, CUtensorMapInterleave, CUtensorMapSwizzle,
                               CUtensorMapL2promotion, CUtensorMapFloatOOBfill);

static void make_map(PFN_encode enc, CUtensorMap* m, const void* base,
                     unsigned long long d0, unsigned long long d1,
                     unsigned long long stride1B, unsigned box0, unsigned box1)
{
    cuuint64_t dims[2]    = { d0, d1 };
    cuuint64_t strides[1] = { stride1B };
    cuuint32_t box[2]     = { box0, box1 };
    cuuint32_t es[2]      = { 1, 1 };
    enc(m, CU_TENSOR_MAP_DATA_TYPE_FLOAT16, 2, (void*)base, dims, strides, box, es,
        CU_TENSOR_MAP_INTERLEAVE_NONE, CU_TENSOR_MAP_SWIZZLE_128B,
        CU_TENSOR_MAP_L2_PROMOTION_L2_128B, CU_TENSOR_MAP_FLOAT_OOB_FILL_NONE);
}

static void make_map_f32(PFN_encode enc, CUtensorMap* m, const void* base,
                         unsigned long long d0, unsigned long long d1,
                         unsigned long long stride1B, unsigned box0, unsigned box1)
{
    cuuint64_t dims[2]    = { d0, d1 };
    cuuint64_t strides[1] = { stride1B };
    cuuint32_t box[2]     = { box0, box1 };
    cuuint32_t es[2]      = { 1, 1 };
    enc(m, CU_TENSOR_MAP_DATA_TYPE_FLOAT32, 2, (void*)base, dims, strides, box, es,
        CU_TENSOR_MAP_INTERLEAVE_NONE, CU_TENSOR_MAP_SWIZZLE_NONE,
        CU_TENSOR_MAP_L2_PROMOTION_L2_128B, CU_TENSOR_MAP_FLOAT_OOB_FILL_NONE);
}

#define SMEM_128 (2048 + 3*(128*128 + 128*128))
#define SMEM_64  (2048 + 3*(128*128 + 64*128))

// ---------------- launch ----------------
extern "C" void kernel_launch(void* const* d_in, const int* in_sizes, int n_in,
                              void* d_out, int out_size)
{
    const float* x    = (const float*)d_in[0];
    const float* x_r  = (const float*)d_in[1];
    const float* x_w  = (const float*)d_in[2];
    const float* x_k  = (const float*)d_in[3];
    const float* x_v  = (const float*)d_in[4];
    const float* x_a  = (const float*)d_in[5];
    const float* x_g  = (const float*)d_in[6];
    const float* w0   = (const float*)d_in[7];
    const float* w1   = (const float*)d_in[8];
    const float* w2   = (const float*)d_in[9];
    const float* a0   = (const float*)d_in[10];
    const float* a1   = (const float*)d_in[11];
    const float* a2   = (const float*)d_in[12];
    const float* g1   = (const float*)d_in[16];
    const float* g2   = (const float*)d_in[17];
    const float* k_k  = (const float*)d_in[18];
    const float* k_a  = (const float*)d_in[19];
    const float* r_k  = (const float*)d_in[20];
    const float* Wr   = (const float*)d_in[21];
    const float* Wk   = (const float*)d_in[22];
    const float* Wv   = (const float*)d_in[23];
    const float* Wo   = (const float*)d_in[24];
    const float* lg   = (const float*)d_in[25];
    const float* lb   = (const float*)d_in[26];

    void *pr, *pk, *pv, *pwd, *pa, *pg, *paa, *pbb, *po;
    void *px6, *pyg, *phid, *pwh;
    cudaGetSymbolAddress(&pr,  g_r);   cudaGetSymbolAddress(&pk,  g_k);
    cudaGetSymbolAddress(&pv,  g_v);   cudaGetSymbolAddress(&pwd, g_wd);
    cudaGetSymbolAddress(&pa,  g_a);   cudaGetSymbolAddress(&pg,  g_g);
    cudaGetSymbolAddress(&paa, g_aa);  cudaGetSymbolAddress(&pbb, g_bb);
    cudaGetSymbolAddress(&po,  g_o);
    cudaGetSymbolAddress(&px6, g_x6);  cudaGetSymbolAddress(&pyg, g_yg);
    cudaGetSymbolAddress(&phid, g_hid);
    cudaGetSymbolAddress(&pwh, g_wh);

    float *rb = (float*)pr, *kb = (float*)pk, *vb = (float*)pv, *wd = (float*)pwd;
    float *ab = (float*)pa, *gb = (float*)pg, *aab = (float*)paa, *bbb = (float*)pbb;
    float *ob = (float*)po;
    f16 *x6 = (f16*)px6, *yg = (f16*)pyg, *hid = (f16*)phid;
    f16 *wh = (f16*)pwh;

    const size_t S = (size_t)BTz * Cz;

    cudaFuncSetAttribute(tc_gemm6<128>, cudaFuncAttributeMaxDynamicSharedMemorySize, SMEM_128);
    cudaFuncSetAttribute(tc_gemm3h<64>, cudaFuncAttributeMaxDynamicSharedMemorySize, SMEM_64);
    cudaFuncSetAttribute(scan_kernel,   cudaFuncAttributeMaxDynamicSharedMemorySize, SCAN_SMEM);

    PFN_encode enc = nullptr;
    cudaDriverEntryPointQueryResult qres;
    cudaGetDriverEntryPoint("cuTensorMapEncodeTiled", (void**)&enc,
                            cudaEnableDefault, &qres);

    // 1. transpose+convert all weights into the pool
    TJobs jb;
    jb.src[0]=Wr; jb.src[1]=Wk; jb.src[2]=Wv; jb.src[3]=Wo;
    jb.src[4]=w1; jb.src[5]=a1; jb.src[6]=g1;
    jb.src[7]=w2; jb.src[8]=a2; jb.src[9]=g2;
    jb.dstoff[0]=O_Wr; jb.dstoff[1]=O_Wk; jb.dstoff[2]=O_Wv; jb.dstoff[3]=O_Wo;
    jb.dstoff[4]=O_L1; jb.dstoff[5]=O_L1+64*Cz; jb.dstoff[6]=O_L1+128*Cz;
    jb.dstoff[7]=O_W2T; jb.dstoff[8]=O_A2T; jb.dstoff[9]=O_G2T;
    jb.K[0]=jb.K[1]=jb.K[2]=jb.K[3]=Cz; jb.K[4]=jb.K[5]=jb.K[6]=Cz;
    jb.K[7]=64; jb.K[8]=64; jb.K[9]=128;
    jb.N[0]=jb.N[1]=jb.N[2]=jb.N[3]=Cz; jb.N[4]=64; jb.N[5]=64; jb.N[6]=128;
    jb.N[7]=Cz; jb.N[8]=Cz; jb.N[9]=Cz;
    int tb = 0;
    for (int j = 0; j < 10; j++) { jb.tbase[j] = tb; tb += (jb.K[j]/32)*(jb.N[j]/32); }
    jb.tbase[10] = tb;
    tsplit_kernel<<<tb, 256>>>(jb, wh);

    // 2. token shift + mix
    mix_kernel<<<(BTz*Cz/4 + 255)/256, 256>>>(x, x_r, x_w, x_k, x_v, x_a, x_g, x6);

    CUtensorMap A0, A1, A2, B0h, B1h, B2h;

    // 3. fused LoRA stage-1: z0 hw=tanh(xw@w1), z1 ha=xa@a1, z2 hg=sig(xg@g1)
    make_map(enc, &A0,  x6 + 1*S, Cz, BTz, Cz*2, 64, 128);
    make_map(enc, &A1,  x6 + 4*S, Cz, BTz, Cz*2, 64, 128);
    make_map(enc, &A2,  x6 + 5*S, Cz, BTz, Cz*2, 64, 128);
    make_map(enc, &B0h, wh + O_L1,          Cz, 64,  Cz*2, 64, 64);
    make_map(enc, &B1h, wh + O_L1 + 64*Cz,  Cz, 64,  Cz*2, 64, 64);
    make_map(enc, &B2h, wh + O_L1 + 128*Cz, Cz, 128, Cz*2, 64, 64);
    tc_gemm3h<64><<<dim3(2, BTz/128, 3), 256, SMEM_64>>>(
        A0, A1, A2, B0h, B1h, B2h,
        hid, hid + 64, hid + 128,
        256, 1, 0, 2, 1, 1, 2);

    // 4. ONE launch: r, k, v projections + LoRA stage-2 (6 jobs)
    G6 g6;
    make_map(enc, &g6.A[0], x6 + 0*S, Cz, BTz, Cz*2, 64, 128);
    make_map(enc, &g6.A[1], x6 + 2*S, Cz, BTz, Cz*2, 64, 128);
    make_map(enc, &g6.A[2], x6 + 3*S, Cz, BTz, Cz*2, 64, 128);
    make_map(enc, &g6.A[3], hid,       64,  BTz, 256*2, 64, 128);
    make_map(enc, &g6.A[4], hid + 64,  64,  BTz, 256*2, 64, 128);
    make_map(enc, &g6.A[5], hid + 128, 128, BTz, 256*2, 64, 128);
    make_map(enc, &g6.Bh[0], wh + O_Wr,  Cz,  Cz, Cz*2,  64, 128);
    make_map(enc, &g6.Bh[1], wh + O_Wk,  Cz,  Cz, Cz*2,  64, 128);
    make_map(enc, &g6.Bh[2], wh + O_Wv,  Cz,  Cz, Cz*2,  64, 128);
    make_map(enc, &g6.Bh[3], wh + O_W2T, 64,  Cz, 64*2,  64, 128);
    make_map(enc, &g6.Bh[4], wh + O_A2T, 64,  Cz, 64*2,  64, 128);
    make_map(enc, &g6.Bh[5], wh + O_G2T, 128, Cz, 128*2, 64, 128);
    g6.K[0] = Cz; g6.K[1] = Cz; g6.K[2] = Cz; g6.K[3] = 64; g6.K[4] = 64; g6.K[5] = 128;
    g6.C[0] = rb; g6.C[1] = kb; g6.C[2] = vb; g6.C[3] = wd; g6.C[4] = ab; g6.C[5] = gb;
    g6.bias[0] = nullptr; g6.bias[1] = nullptr; g6.bias[2] = nullptr;
    g6.bias[3] = w0; g6.bias[4] = a0; g6.bias[5] = nullptr;
    g6.epi[0] = 0; g6.epi[1] = 0; g6.epi[2] = 0; g6.epi[3] = 3; g6.epi[4] = 2; g6.epi[5] = 0;
    tc_gemm6<128><<<dim3(8, BTz/128, 6), 256, SMEM_128>>>(g6, Cz);

    // 5. kk normalize / aa / bb / k update (parallel)
    prep_kernel<<<BTz*Hz/8, 256>>>(k_k, k_a);

    // 6. sequential scan (TMA-batched, row-split)
    {
        CUtensorMap sR, sW, sK, sAA, sBB, sV;
        make_map_f32(enc, &sR,  rb,  Cz, BTz, Cz*4, 64, STB);
        make_map_f32(enc, &sW,  wd,  Cz, BTz, Cz*4, 64, STB);
        make_map_f32(enc, &sK,  kb,  Cz, BTz, Cz*4, 64, STB);
        make_map_f32(enc, &sAA, aab, Cz, BTz, Cz*4, 64, STB);
        make_map_f32(enc, &sBB, bbb, Cz, BTz, Cz*4, 64, STB);
        make_map_f32(enc, &sV,  vb,  Cz, BTz, Cz*4, 64, STB);
        scan_kernel<<<dim3(Bz*Hz, RSPLIT), 256, SCAN_SMEM>>>(sR, sW, sK, sAA, sBB, sV, ob);
    }

    // 7. groupnorm + bonus + gate -> yg fp16
    post_kernel<<<BTz*Hz/8, 256>>>(r_k, lg, lb);

    // 8. output projection (1 job)
    G6 go;
    make_map(enc, &go.A[0],  yg, Cz, BTz, Cz*2, 64, 128);
    make_map(enc, &go.Bh[0], wh + O_Wo, Cz, Cz, Cz*2, 64, 128);
    for (int z = 1; z < 6; z++) { go.A[z] = go.A[0]; go.Bh[z] = go.Bh[0]; }
    for (int z = 0; z < 6; z++) { go.K[z] = Cz; go.C[z] = (float*)d_out; go.bias[z] = nullptr; go.epi[z] = 0; }
    tc_gemm6<128><<<dim3(8, BTz/128, 1), 256, SMEM_128>>>(go, Cz);

    // 9. v_first if expected
    if (out_size >= 2 * BTz * Cz) {
        cudaMemcpyAsync((float*)d_out + S, vb, sizeof(float) * S, cudaMemcpyDeviceToDevice);
    }
}